// round 2
// baseline (speedup 1.0000x reference)
#include <cuda_runtime.h>
#include <math.h>

#define NB 256
#define NT 10
#define BT 2560
#define NP 49
#define VDIM 512
#define QDIM 128
#define HDIM 256
#define ADIM 128

// vf2 scratch: 2560*49*512 floats (~257 MB). Static device array (no runtime alloc).
static __device__ float g_vf2[(size_t)BT * NP * VDIM];

__device__ __forceinline__ float wsum(float v){
#pragma unroll
    for (int s = 16; s > 0; s >>= 1) v += __shfl_xor_sync(0xffffffffu, v, s);
    return v;
}
__device__ __forceinline__ float wmax(float v){
#pragma unroll
    for (int s = 16; s > 0; s >>= 1) v = fmaxf(v, __shfl_xor_sync(0xffffffffu, v, s));
    return v;
}

// ---------------------------------------------------------------------------
// Kernel 1: per-item visual self-attention + residual + LayerNorm -> g_vf2
// ---------------------------------------------------------------------------
__global__ void __launch_bounds__(256, 1)
k1(const float* __restrict__ video,
   const float* __restrict__ wq, const float* __restrict__ bq,
   const float* __restrict__ wk, const float* __restrict__ bk,
   const float* __restrict__ wv, const float* __restrict__ bv,
   const float* __restrict__ ln_g, const float* __restrict__ ln_b)
{
    extern __shared__ float sm[];
    float* sX    = sm;                   // 49*512 raw vf, becomes vf+out
    float* sO    = sm + NP * VDIM;       // 49*512: q/k (stride 129), then avf
    float* sAttn = sO + NP * VDIM;       // 49*52

    const int tid  = threadIdx.x;
    const int item = blockIdx.x;
    const float* vf = video + (size_t)item * NP * VDIM;

    for (int i = tid; i < NP * VDIM / 4; i += 256)
        ((float4*)sX)[i] = ((const float4*)vf)[i];
    __syncthreads();

    // ---- q, k : thread owns one output column j (q: tid<128, k: tid>=128) ----
    {
        const int j = tid & 127;
        const float* W = (tid < 128) ? wq : wk;
        const float  b = (tid < 128) ? bq[j] : bk[j];
        float acc[NP];
#pragma unroll
        for (int n = 0; n < NP; n++) acc[n] = 0.f;
        const float4* wrow = (const float4*)(W + (size_t)j * VDIM);
        for (int c4 = 0; c4 < VDIM / 4; c4++){
            float4 w = wrow[c4];
#pragma unroll
            for (int n = 0; n < NP; n++){
                float4 x = ((const float4*)(sX + n * VDIM))[c4];
                acc[n] = fmaf(x.x, w.x, fmaf(x.y, w.y, fmaf(x.z, w.z, fmaf(x.w, w.w, acc[n]))));
            }
        }
        float* dst = sO + ((tid < 128) ? 0 : NP * 129);
#pragma unroll
        for (int n = 0; n < NP; n++) dst[n * 129 + j] = acc[n] + b;
    }
    __syncthreads();

    // ---- attn = softmax(q k^T), one warp per row n ----
    {
        const int w = tid >> 5, l = tid & 31;
        const float* sQ = sO;
        const float* sK = sO + NP * 129;
        for (int n = w; n < NP; n += 8){
            float a0 = 0.f, a1 = 0.f;
            const int m1  = l + 32;
            const int m1c = (m1 < NP) ? m1 : 0;
            for (int j = 0; j < QDIM; j++){
                float q = sQ[n * 129 + j];
                a0 = fmaf(q, sK[l   * 129 + j], a0);
                a1 = fmaf(q, sK[m1c * 129 + j], a1);
            }
            float v1 = (m1 < NP) ? a1 : -1e30f;
            float mx = wmax(fmaxf(a0, v1));
            float e0 = expf(a0 - mx);
            float e1 = (m1 < NP) ? expf(a1 - mx) : 0.f;
            float s  = wsum(e0 + e1);
            float inv = 1.f / s;
            sAttn[n * 52 + l] = e0 * inv;
            if (m1 < NP) sAttn[n * 52 + m1] = e1 * inv;
        }
    }
    __syncthreads();

    // ---- avf = attn @ X  -> sO (q/k dead) ----
    for (int p = 0; p < 2; p++){
        const int c = tid + p * 256;
        float acc[NP];
#pragma unroll
        for (int n = 0; n < NP; n++) acc[n] = 0.f;
        for (int m = 0; m < NP; m++){
            float x = sX[m * VDIM + c];
#pragma unroll
            for (int n = 0; n < NP; n++) acc[n] = fmaf(sAttn[n * 52 + m], x, acc[n]);
        }
#pragma unroll
        for (int n = 0; n < NP; n++) sO[n * VDIM + c] = acc[n];
    }
    __syncthreads();

    // ---- out = avf @ wv^T + bv (rows of attn sum to 1, so bias is exact);
    //      X += out (residual, in place) ----
    for (int p = 0; p < 2; p++){
        const int j = tid + p * 256;
        float acc[NP];
#pragma unroll
        for (int n = 0; n < NP; n++) acc[n] = 0.f;
        const float4* wrow = (const float4*)(wv + (size_t)j * VDIM);
        for (int c4 = 0; c4 < VDIM / 4; c4++){
            float4 w = wrow[c4];
#pragma unroll
            for (int n = 0; n < NP; n++){
                float4 x = ((const float4*)(sO + n * VDIM))[c4];
                acc[n] = fmaf(x.x, w.x, fmaf(x.y, w.y, fmaf(x.z, w.z, fmaf(x.w, w.w, acc[n]))));
            }
        }
        float b = bv[j];
#pragma unroll
        for (int n = 0; n < NP; n++) sX[n * VDIM + j] += acc[n] + b;
    }
    __syncthreads();

    // ---- LayerNorm rows -> g_vf2 ----
    {
        const int w = tid >> 5, l = tid & 31;
        float* gout = g_vf2 + (size_t)item * NP * VDIM;
        for (int n = w; n < NP; n += 8){
            float s = 0.f, s2 = 0.f;
            for (int j = l; j < VDIM; j += 32){
                float v = sX[n * VDIM + j];
                s += v; s2 = fmaf(v, v, s2);
            }
            s = wsum(s); s2 = wsum(s2);
            float mu  = s * (1.f / VDIM);
            float var = s2 * (1.f / VDIM) - mu * mu;
            float rs  = rsqrtf(var + 1e-5f);
            for (int j = l; j < VDIM; j += 32)
                gout[n * VDIM + j] = (sX[n * VDIM + j] - mu) * rs * ln_g[j] + ln_b[j];
        }
    }
}

// ---------------------------------------------------------------------------
// Kernel 2: all remaining branches, fully fused per item
// ---------------------------------------------------------------------------
__global__ void __launch_bounds__(256, 1)
k2(const float* __restrict__ video, const float* __restrict__ audio,
   const float* __restrict__ w_ave, const float* __restrict__ b_ave,
   const float* __restrict__ w_v3, const float* __restrict__ b_v3,
   const float* __restrict__ w_avatt, const float* __restrict__ b_avatt,
   const float* __restrict__ w_a1, const float* __restrict__ b_a1,
   const float* __restrict__ w_v1, const float* __restrict__ b_v1,
   const float* __restrict__ w_bn, const float* __restrict__ b_bn,
   const float* __restrict__ w_ca, const float* __restrict__ b_ca,
   const float* __restrict__ w_v2, const float* __restrict__ b_v2,
   const float* __restrict__ w_a2, const float* __restrict__ b_a2,
   const float* __restrict__ w_sa, const float* __restrict__ b_sa,
   float* __restrict__ out)
{
    extern __shared__ float sm[];
    float* sV   = sm;                  // 49*512 vf2
    float* sR   = sm + NP * VDIM;      // 49*512 raw vf -> c_att (in place)
    float* colm = sm + 2 * NP * VDIM;  // 512
    float* aq1  = colm + 512;          // 512
    float* ch   = aq1 + 512;           // 512
    float* colv = ch + 512;            // 512
    float* havg = colv + 512;          // 256
    float* aq2  = havg + 256;          // 256
    float* avqv = aq2 + 256;           // 256
    float* aud  = avqv + 256;          // 128
    float* sSelf= aud + 128;           // 64
    float* sSp  = sSelf + 64;          // 64

    const int tid  = threadIdx.x;
    const int item = blockIdx.x;
    const int bb = item / NT, tt = item % NT;

    const float4* gv2 = (const float4*)(g_vf2 + (size_t)item * NP * VDIM);
    const float4* grw = (const float4*)(video + (size_t)item * NP * VDIM);
    for (int i = tid; i < NP * VDIM / 4; i += 256){
        ((float4*)sV)[i] = gv2[i];
        ((float4*)sR)[i] = grw[i];
    }
    const float* ap = audio + ((size_t)tt * NB + bb) * ADIM;   // audio[T,B,AD] -> [b,t]
    if (tid < 32) ((float4*)aud)[tid] = ((const float4*)ap)[tid];
    if (tid < NP){ sSelf[tid] = b_avatt[0]; sSp[tid] = b_sa[0]; }
    __syncthreads();

    // ---- P1: column mean of vf2, aq1 = relu(W_a1 aud), aq2 = relu(W_a2 aud) ----
    for (int p = 0; p < 2; p++){
        int c = tid + p * 256;
        float s = 0.f;
        for (int n = 0; n < NP; n++) s += sV[n * VDIM + c];
        colm[c] = s * (1.f / NP);
        const float4* wr = (const float4*)(w_a1 + (size_t)c * ADIM);
        float a = 0.f;
        for (int k = 0; k < ADIM / 4; k++){
            float4 w = wr[k]; float4 x = ((const float4*)aud)[k];
            a = fmaf(w.x, x.x, fmaf(w.y, x.y, fmaf(w.z, x.z, fmaf(w.w, x.w, a))));
        }
        aq1[c] = fmaxf(a + b_a1[c], 0.f);
    }
    {
        const float4* wr = (const float4*)(w_a2 + (size_t)tid * ADIM);
        float a = 0.f;
        for (int k = 0; k < ADIM / 4; k++){
            float4 w = wr[k]; float4 x = ((const float4*)aud)[k];
            a = fmaf(w.x, x.x, fmaf(w.y, x.y, fmaf(w.z, x.z, fmaf(w.w, x.w, a))));
        }
        aq2[tid] = fmaxf(a + b_a2[tid], 0.f);
    }
    __syncthreads();

    // ---- P2: havg = relu(W_ave colm) ----
    {
        const float4* wr = (const float4*)(w_ave + (size_t)tid * VDIM);
        float a = 0.f;
        for (int k = 0; k < VDIM / 4; k++){
            float4 w = wr[k]; float4 x = ((const float4*)colm)[k];
            a = fmaf(w.x, x.x, fmaf(w.y, x.y, fmaf(w.z, x.z, fmaf(w.w, x.w, a))));
        }
        havg[tid] = fmaxf(a + b_ave[tid], 0.f);
    }
    __syncthreads();

    // ---- P3a: self branch GEMM (w_v3), fused into self-attn logits ----
    {
        const int j = tid;                       // HD == 256 == blockDim
        float acc[NP];
#pragma unroll
        for (int n = 0; n < NP; n++) acc[n] = 0.f;
        const float4* wrow = (const float4*)(w_v3 + (size_t)j * VDIM);
        for (int c4 = 0; c4 < VDIM / 4; c4++){
            float4 w = wrow[c4];
#pragma unroll
            for (int n = 0; n < NP; n++){
                float4 x = ((const float4*)(sV + n * VDIM))[c4];
                acc[n] = fmaf(x.x, w.x, fmaf(x.y, w.y, fmaf(x.z, w.z, fmaf(x.w, w.w, acc[n]))));
            }
        }
        const float bj = b_v3[j];
        const float scale = havg[j] * w_avatt[j];
#pragma unroll
        for (int n = 0; n < NP; n++){
            float v = fmaxf(acc[n] + bj, 0.f) * scale;
            v = wsum(v);
            if ((tid & 31) == 0) atomicAdd(&sSelf[n], v);
        }
    }
    // ---- P3b: vq1 GEMM (w_v1), fused column mean -> colv = aq1 * mean_n relu(.) ----
    for (int p = 0; p < 2; p++){
        const int c = tid + p * 256;
        float acc[NP];
#pragma unroll
        for (int n = 0; n < NP; n++) acc[n] = 0.f;
        const float4* wrow = (const float4*)(w_v1 + (size_t)c * VDIM);
        for (int c4 = 0; c4 < VDIM / 4; c4++){
            float4 w = wrow[c4];
#pragma unroll
            for (int n = 0; n < NP; n++){
                float4 x = ((const float4*)(sV + n * VDIM))[c4];
                acc[n] = fmaf(x.x, w.x, fmaf(x.y, w.y, fmaf(x.z, w.z, fmaf(x.w, w.w, acc[n]))));
            }
        }
        const float bc = b_v1[c];
        float s = 0.f;
#pragma unroll
        for (int n = 0; n < NP; n++) s += fmaxf(acc[n] + bc, 0.f);
        colv[c] = s * (1.f / NP) * aq1[c];
    }
    __syncthreads();

    // ---- P4: avq = relu(W_bn colv); warp0: self_maps = softmax(tanh(logits)) ----
    {
        const float4* wr = (const float4*)(w_bn + (size_t)tid * VDIM);
        float a = 0.f;
        for (int k = 0; k < VDIM / 4; k++){
            float4 w = wr[k]; float4 x = ((const float4*)colv)[k];
            a = fmaf(w.x, x.x, fmaf(w.y, x.y, fmaf(w.z, x.z, fmaf(w.w, x.w, a))));
        }
        avqv[tid] = fmaxf(a + b_bn[tid], 0.f);
    }
    if (tid < 32){
        float v0 = tanhf(sSelf[tid]);
        float v1 = (tid + 32 < NP) ? tanhf(sSelf[tid + 32]) : -1e30f;
        float mx = wmax(fmaxf(v0, v1));
        float e0 = expf(v0 - mx);
        float e1 = (tid + 32 < NP) ? expf(v1 - mx) : 0.f;
        float s  = wsum(e0 + e1);
        sSelf[tid] = e0 / s;
        if (tid + 32 < NP) sSelf[tid + 32] = e1 / s;
    }
    __syncthreads();

    // ---- P5: ch = sigmoid(W_ca avq) + 1 ----
    for (int p = 0; p < 2; p++){
        int c = tid + p * 256;
        const float4* wr = (const float4*)(w_ca + (size_t)c * HDIM);
        float a = 0.f;
        for (int k = 0; k < HDIM / 4; k++){
            float4 w = wr[k]; float4 x = ((const float4*)avqv)[k];
            a = fmaf(w.x, x.x, fmaf(w.y, x.y, fmaf(w.z, x.z, fmaf(w.w, x.w, a))));
        }
        ch[c] = 1.f + 1.f / (1.f + expf(-(a + b_ca[c])));
    }
    __syncthreads();

    // ---- P6: c_att = raw * ch, in place over sR ----
    for (int i = tid; i < NP * VDIM / 4; i += 256){
        int c4i = i & 127;
        float4 r = ((float4*)sR)[i];
        float4 m = ((const float4*)ch)[c4i];
        r.x *= m.x; r.y *= m.y; r.z *= m.z; r.w *= m.w;
        ((float4*)sR)[i] = r;
    }
    __syncthreads();

    // ---- P7: cq GEMM (w_v2) fused into spatial-attn logits ----
    {
        const int j = tid;
        float acc[NP];
#pragma unroll
        for (int n = 0; n < NP; n++) acc[n] = 0.f;
        const float4* wrow = (const float4*)(w_v2 + (size_t)j * VDIM);
        for (int c4 = 0; c4 < VDIM / 4; c4++){
            float4 w = wrow[c4];
#pragma unroll
            for (int n = 0; n < NP; n++){
                float4 x = ((const float4*)(sR + n * VDIM))[c4];
                acc[n] = fmaf(x.x, w.x, fmaf(x.y, w.y, fmaf(x.z, w.z, fmaf(x.w, w.w, acc[n]))));
            }
        }
        const float bj = b_v2[j];
        const float scale = aq2[j] * w_sa[j];
#pragma unroll
        for (int n = 0; n < NP; n++){
            float v = fmaxf(acc[n] + bj, 0.f) * scale;
            v = wsum(v);
            if ((tid & 31) == 0) atomicAdd(&sSp[n], v);
        }
    }
    __syncthreads();

    // ---- P8: sp_maps = softmax(tanh(logits)) ----
    if (tid < 32){
        float v0 = tanhf(sSp[tid]);
        float v1 = (tid + 32 < NP) ? tanhf(sSp[tid + 32]) : -1e30f;
        float mx = wmax(fmaxf(v0, v1));
        float e0 = expf(v0 - mx);
        float e1 = (tid + 32 < NP) ? expf(v1 - mx) : 0.f;
        float s  = wsum(e0 + e1);
        sSp[tid] = e0 / s;
        if (tid + 32 < NP) sSp[tid + 32] = e1 / s;
    }
    __syncthreads();

    // ---- P9: outputs ----
    for (int p = 0; p < 2; p++){
        int c = tid + p * 256;
        float sa = 0.f, cs = 0.f;
        for (int n = 0; n < NP; n++){
            sa = fmaf(sSelf[n], sV[n * VDIM + c], sa);
            cs = fmaf(sSp[n],   sR[n * VDIM + c], cs);
        }
        float g = 1.f + 0.5f / (1.f + expf(-sa));
        out[(size_t)item * VDIM + c] = cs * g;
    }
    if (tid < ADIM)
        out[(size_t)BT * VDIM + (size_t)item * ADIM + tid] = aud[tid];
}

// ---------------------------------------------------------------------------
extern "C" void kernel_launch(void* const* d_in, const int* in_sizes, int n_in,
                              void* d_out, int out_size)
{
    const float* video = (const float*)d_in[0];
    const float* audio = (const float*)d_in[1];
    const float* wq    = (const float*)d_in[2];  const float* bq    = (const float*)d_in[3];
    const float* wk    = (const float*)d_in[4];  const float* bk    = (const float*)d_in[5];
    const float* wv    = (const float*)d_in[6];  const float* bv    = (const float*)d_in[7];
    const float* ln_g  = (const float*)d_in[8];  const float* ln_b  = (const float*)d_in[9];
    const float* w_ave = (const float*)d_in[10]; const float* b_ave = (const float*)d_in[11];
    const float* w_v3  = (const float*)d_in[12]; const float* b_v3  = (const float*)d_in[13];
    const float* w_avt = (const float*)d_in[14]; const float* b_avt = (const float*)d_in[15];
    const float* w_a1  = (const float*)d_in[16]; const float* b_a1  = (const float*)d_in[17];
    const float* w_v1  = (const float*)d_in[18]; const float* b_v1  = (const float*)d_in[19];
    const float* w_bn  = (const float*)d_in[20]; const float* b_bn  = (const float*)d_in[21];
    const float* w_ca  = (const float*)d_in[22]; const float* b_ca  = (const float*)d_in[23];
    const float* w_v2  = (const float*)d_in[24]; const float* b_v2  = (const float*)d_in[25];
    const float* w_a2  = (const float*)d_in[26]; const float* b_a2  = (const float*)d_in[27];
    const float* w_sa  = (const float*)d_in[28]; const float* b_sa  = (const float*)d_in[29];
    float* out = (float*)d_out;

    const int smem1 = (NP * VDIM * 2 + NP * 52) * (int)sizeof(float);   // ~211 KB
    const int smem2 = (NP * VDIM * 2 + 3072) * (int)sizeof(float);      // ~213 KB
    cudaFuncSetAttribute(k1, cudaFuncAttributeMaxDynamicSharedMemorySize, smem1);
    cudaFuncSetAttribute(k2, cudaFuncAttributeMaxDynamicSharedMemorySize, smem2);

    k1<<<BT, 256, smem1>>>(video, wq, bq, wk, bk, wv, bv, ln_g, ln_b);
    k2<<<BT, 256, smem2>>>(video, audio, w_ave, b_ave, w_v3, b_v3, w_avt, b_avt,
                           w_a1, b_a1, w_v1, b_v1, w_bn, b_bn, w_ca, b_ca,
                           w_v2, b_v2, w_a2, b_a2, w_sa, b_sa, out);
}

// round 3
// speedup vs baseline: 1.0008x; 1.0008x over previous
#include <cuda_runtime.h>
#include <math.h>

#define NB 256
#define NT 10
#define BT 2560
#define NP 49
#define VDIM 512
#define QDIM 128
#define HDIM 256
#define ADIM 128

// vf2 scratch: 2560*49*512 floats (~257 MB). Static device array (no runtime alloc).
static __device__ float g_vf2[(size_t)BT * NP * VDIM];

__device__ __forceinline__ float wsum(float v){
#pragma unroll
    for (int s = 16; s > 0; s >>= 1) v += __shfl_xor_sync(0xffffffffu, v, s);
    return v;
}
__device__ __forceinline__ float wmax(float v){
#pragma unroll
    for (int s = 16; s > 0; s >>= 1) v = fmaxf(v, __shfl_xor_sync(0xffffffffu, v, s));
    return v;
}

// ---------------------------------------------------------------------------
// Kernel 1: per-item visual self-attention + residual + LayerNorm -> g_vf2
// ---------------------------------------------------------------------------
__global__ void __launch_bounds__(256, 1)
k1(const float* __restrict__ video,
   const float* __restrict__ wq, const float* __restrict__ bq,
   const float* __restrict__ wk, const float* __restrict__ bk,
   const float* __restrict__ wv, const float* __restrict__ bv,
   const float* __restrict__ ln_g, const float* __restrict__ ln_b)
{
    extern __shared__ float sm[];
    float* sX    = sm;                   // 49*512 raw vf, becomes vf+out
    float* sO    = sm + NP * VDIM;       // 49*512: q/k (stride 129), then avf
    float* sAttn = sO + NP * VDIM;       // 49*52

    const int tid  = threadIdx.x;
    const int item = blockIdx.x;
    const float* vf = video + (size_t)item * NP * VDIM;

    for (int i = tid; i < NP * VDIM / 4; i += 256)
        ((float4*)sX)[i] = ((const float4*)vf)[i];
    __syncthreads();

    // ---- q, k : thread owns one output column j (q: tid<128, k: tid>=128) ----
    {
        const int j = tid & 127;
        const float* W = (tid < 128) ? wq : wk;
        const float  b = (tid < 128) ? bq[j] : bk[j];
        float acc[NP];
#pragma unroll
        for (int n = 0; n < NP; n++) acc[n] = 0.f;
        const float4* wrow = (const float4*)(W + (size_t)j * VDIM);
        for (int c4 = 0; c4 < VDIM / 4; c4++){
            float4 w = wrow[c4];
#pragma unroll
            for (int n = 0; n < NP; n++){
                float4 x = ((const float4*)(sX + n * VDIM))[c4];
                acc[n] = fmaf(x.x, w.x, fmaf(x.y, w.y, fmaf(x.z, w.z, fmaf(x.w, w.w, acc[n]))));
            }
        }
        float* dst = sO + ((tid < 128) ? 0 : NP * 129);
#pragma unroll
        for (int n = 0; n < NP; n++) dst[n * 129 + j] = acc[n] + b;
    }
    __syncthreads();

    // ---- attn = softmax(q k^T), one warp per row n ----
    {
        const int w = tid >> 5, l = tid & 31;
        const float* sQ = sO;
        const float* sK = sO + NP * 129;
        for (int n = w; n < NP; n += 8){
            float a0 = 0.f, a1 = 0.f;
            const int m1  = l + 32;
            const int m1c = (m1 < NP) ? m1 : 0;
            for (int j = 0; j < QDIM; j++){
                float q = sQ[n * 129 + j];
                a0 = fmaf(q, sK[l   * 129 + j], a0);
                a1 = fmaf(q, sK[m1c * 129 + j], a1);
            }
            float v1 = (m1 < NP) ? a1 : -1e30f;
            float mx = wmax(fmaxf(a0, v1));
            float e0 = expf(a0 - mx);
            float e1 = (m1 < NP) ? expf(a1 - mx) : 0.f;
            float s  = wsum(e0 + e1);
            float inv = 1.f / s;
            sAttn[n * 52 + l] = e0 * inv;
            if (m1 < NP) sAttn[n * 52 + m1] = e1 * inv;
        }
    }
    __syncthreads();

    // ---- avf = attn @ X  -> sO (q/k dead) ----
    for (int p = 0; p < 2; p++){
        const int c = tid + p * 256;
        float acc[NP];
#pragma unroll
        for (int n = 0; n < NP; n++) acc[n] = 0.f;
        for (int m = 0; m < NP; m++){
            float x = sX[m * VDIM + c];
#pragma unroll
            for (int n = 0; n < NP; n++) acc[n] = fmaf(sAttn[n * 52 + m], x, acc[n]);
        }
#pragma unroll
        for (int n = 0; n < NP; n++) sO[n * VDIM + c] = acc[n];
    }
    __syncthreads();

    // ---- out = avf @ wv^T + bv (rows of attn sum to 1, so bias is exact);
    //      X += out (residual, in place) ----
    for (int p = 0; p < 2; p++){
        const int j = tid + p * 256;
        float acc[NP];
#pragma unroll
        for (int n = 0; n < NP; n++) acc[n] = 0.f;
        const float4* wrow = (const float4*)(wv + (size_t)j * VDIM);
        for (int c4 = 0; c4 < VDIM / 4; c4++){
            float4 w = wrow[c4];
#pragma unroll
            for (int n = 0; n < NP; n++){
                float4 x = ((const float4*)(sO + n * VDIM))[c4];
                acc[n] = fmaf(x.x, w.x, fmaf(x.y, w.y, fmaf(x.z, w.z, fmaf(x.w, w.w, acc[n]))));
            }
        }
        float b = bv[j];
#pragma unroll
        for (int n = 0; n < NP; n++) sX[n * VDIM + j] += acc[n] + b;
    }
    __syncthreads();

    // ---- LayerNorm rows -> g_vf2 ----
    {
        const int w = tid >> 5, l = tid & 31;
        float* gout = g_vf2 + (size_t)item * NP * VDIM;
        for (int n = w; n < NP; n += 8){
            float s = 0.f, s2 = 0.f;
            for (int j = l; j < VDIM; j += 32){
                float v = sX[n * VDIM + j];
                s += v; s2 = fmaf(v, v, s2);
            }
            s = wsum(s); s2 = wsum(s2);
            float mu  = s * (1.f / VDIM);
            float var = s2 * (1.f / VDIM) - mu * mu;
            float rs  = rsqrtf(var + 1e-5f);
            for (int j = l; j < VDIM; j += 32)
                gout[n * VDIM + j] = (sX[n * VDIM + j] - mu) * rs * ln_g[j] + ln_b[j];
        }
    }
}

// ---------------------------------------------------------------------------
// Kernel 2: all remaining branches, fully fused per item
// ---------------------------------------------------------------------------
__global__ void __launch_bounds__(256, 1)
k2(const float* __restrict__ video, const float* __restrict__ audio,
   const float* __restrict__ w_ave, const float* __restrict__ b_ave,
   const float* __restrict__ w_v3, const float* __restrict__ b_v3,
   const float* __restrict__ w_avatt, const float* __restrict__ b_avatt,
   const float* __restrict__ w_a1, const float* __restrict__ b_a1,
   const float* __restrict__ w_v1, const float* __restrict__ b_v1,
   const float* __restrict__ w_bn, const float* __restrict__ b_bn,
   const float* __restrict__ w_ca, const float* __restrict__ b_ca,
   const float* __restrict__ w_v2, const float* __restrict__ b_v2,
   const float* __restrict__ w_a2, const float* __restrict__ b_a2,
   const float* __restrict__ w_sa, const float* __restrict__ b_sa,
   float* __restrict__ out)
{
    extern __shared__ float sm[];
    float* sV   = sm;                  // 49*512 vf2
    float* sR   = sm + NP * VDIM;      // 49*512 raw vf -> c_att (in place)
    float* colm = sm + 2 * NP * VDIM;  // 512
    float* aq1  = colm + 512;          // 512
    float* ch   = aq1 + 512;           // 512
    float* colv = ch + 512;            // 512
    float* havg = colv + 512;          // 256
    float* aq2  = havg + 256;          // 256
    float* avqv = aq2 + 256;           // 256
    float* aud  = avqv + 256;          // 128
    float* sSelf= aud + 128;           // 64
    float* sSp  = sSelf + 64;          // 64

    const int tid  = threadIdx.x;
    const int item = blockIdx.x;
    const int bb = item / NT, tt = item % NT;

    const float4* gv2 = (const float4*)(g_vf2 + (size_t)item * NP * VDIM);
    const float4* grw = (const float4*)(video + (size_t)item * NP * VDIM);
    for (int i = tid; i < NP * VDIM / 4; i += 256){
        ((float4*)sV)[i] = gv2[i];
        ((float4*)sR)[i] = grw[i];
    }
    const float* ap = audio + ((size_t)tt * NB + bb) * ADIM;   // audio[T,B,AD] -> [b,t]
    if (tid < 32) ((float4*)aud)[tid] = ((const float4*)ap)[tid];
    if (tid < NP){ sSelf[tid] = b_avatt[0]; sSp[tid] = b_sa[0]; }
    __syncthreads();

    // ---- P1: column mean of vf2, aq1 = relu(W_a1 aud), aq2 = relu(W_a2 aud) ----
    for (int p = 0; p < 2; p++){
        int c = tid + p * 256;
        float s = 0.f;
        for (int n = 0; n < NP; n++) s += sV[n * VDIM + c];
        colm[c] = s * (1.f / NP);
        const float4* wr = (const float4*)(w_a1 + (size_t)c * ADIM);
        float a = 0.f;
        for (int k = 0; k < ADIM / 4; k++){
            float4 w = wr[k]; float4 x = ((const float4*)aud)[k];
            a = fmaf(w.x, x.x, fmaf(w.y, x.y, fmaf(w.z, x.z, fmaf(w.w, x.w, a))));
        }
        aq1[c] = fmaxf(a + b_a1[c], 0.f);
    }
    {
        const float4* wr = (const float4*)(w_a2 + (size_t)tid * ADIM);
        float a = 0.f;
        for (int k = 0; k < ADIM / 4; k++){
            float4 w = wr[k]; float4 x = ((const float4*)aud)[k];
            a = fmaf(w.x, x.x, fmaf(w.y, x.y, fmaf(w.z, x.z, fmaf(w.w, x.w, a))));
        }
        aq2[tid] = fmaxf(a + b_a2[tid], 0.f);
    }
    __syncthreads();

    // ---- P2: havg = relu(W_ave colm) ----
    {
        const float4* wr = (const float4*)(w_ave + (size_t)tid * VDIM);
        float a = 0.f;
        for (int k = 0; k < VDIM / 4; k++){
            float4 w = wr[k]; float4 x = ((const float4*)colm)[k];
            a = fmaf(w.x, x.x, fmaf(w.y, x.y, fmaf(w.z, x.z, fmaf(w.w, x.w, a))));
        }
        havg[tid] = fmaxf(a + b_ave[tid], 0.f);
    }
    __syncthreads();

    // ---- P3a: self branch GEMM (w_v3), fused into self-attn logits ----
    {
        const int j = tid;                       // HD == 256 == blockDim
        float acc[NP];
#pragma unroll
        for (int n = 0; n < NP; n++) acc[n] = 0.f;
        const float4* wrow = (const float4*)(w_v3 + (size_t)j * VDIM);
        for (int c4 = 0; c4 < VDIM / 4; c4++){
            float4 w = wrow[c4];
#pragma unroll
            for (int n = 0; n < NP; n++){
                float4 x = ((const float4*)(sV + n * VDIM))[c4];
                acc[n] = fmaf(x.x, w.x, fmaf(x.y, w.y, fmaf(x.z, w.z, fmaf(x.w, w.w, acc[n]))));
            }
        }
        const float bj = b_v3[j];
        const float scale = havg[j] * w_avatt[j];
#pragma unroll
        for (int n = 0; n < NP; n++){
            float v = fmaxf(acc[n] + bj, 0.f) * scale;
            v = wsum(v);
            if ((tid & 31) == 0) atomicAdd(&sSelf[n], v);
        }
    }
    // ---- P3b: vq1 GEMM (w_v1), fused column mean -> colv = aq1 * mean_n relu(.) ----
    for (int p = 0; p < 2; p++){
        const int c = tid + p * 256;
        float acc[NP];
#pragma unroll
        for (int n = 0; n < NP; n++) acc[n] = 0.f;
        const float4* wrow = (const float4*)(w_v1 + (size_t)c * VDIM);
        for (int c4 = 0; c4 < VDIM / 4; c4++){
            float4 w = wrow[c4];
#pragma unroll
            for (int n = 0; n < NP; n++){
                float4 x = ((const float4*)(sV + n * VDIM))[c4];
                acc[n] = fmaf(x.x, w.x, fmaf(x.y, w.y, fmaf(x.z, w.z, fmaf(x.w, w.w, acc[n]))));
            }
        }
        const float bc = b_v1[c];
        float s = 0.f;
#pragma unroll
        for (int n = 0; n < NP; n++) s += fmaxf(acc[n] + bc, 0.f);
        colv[c] = s * (1.f / NP) * aq1[c];
    }
    __syncthreads();

    // ---- P4: avq = relu(W_bn colv); warp0: self_maps = softmax(tanh(logits)) ----
    {
        const float4* wr = (const float4*)(w_bn + (size_t)tid * VDIM);
        float a = 0.f;
        for (int k = 0; k < VDIM / 4; k++){
            float4 w = wr[k]; float4 x = ((const float4*)colv)[k];
            a = fmaf(w.x, x.x, fmaf(w.y, x.y, fmaf(w.z, x.z, fmaf(w.w, x.w, a))));
        }
        avqv[tid] = fmaxf(a + b_bn[tid], 0.f);
    }
    if (tid < 32){
        float v0 = tanhf(sSelf[tid]);
        float v1 = (tid + 32 < NP) ? tanhf(sSelf[tid + 32]) : -1e30f;
        float mx = wmax(fmaxf(v0, v1));
        float e0 = expf(v0 - mx);
        float e1 = (tid + 32 < NP) ? expf(v1 - mx) : 0.f;
        float s  = wsum(e0 + e1);
        sSelf[tid] = e0 / s;
        if (tid + 32 < NP) sSelf[tid + 32] = e1 / s;
    }
    __syncthreads();

    // ---- P5: ch = sigmoid(W_ca avq) + 1 ----
    for (int p = 0; p < 2; p++){
        int c = tid + p * 256;
        const float4* wr = (const float4*)(w_ca + (size_t)c * HDIM);
        float a = 0.f;
        for (int k = 0; k < HDIM / 4; k++){
            float4 w = wr[k]; float4 x = ((const float4*)avqv)[k];
            a = fmaf(w.x, x.x, fmaf(w.y, x.y, fmaf(w.z, x.z, fmaf(w.w, x.w, a))));
        }
        ch[c] = 1.f + 1.f / (1.f + expf(-(a + b_ca[c])));
    }
    __syncthreads();

    // ---- P6: c_att = raw * ch, in place over sR ----
    for (int i = tid; i < NP * VDIM / 4; i += 256){
        int c4i = i & 127;
        float4 r = ((float4*)sR)[i];
        float4 m = ((const float4*)ch)[c4i];
        r.x *= m.x; r.y *= m.y; r.z *= m.z; r.w *= m.w;
        ((float4*)sR)[i] = r;
    }
    __syncthreads();

    // ---- P7: cq GEMM (w_v2) fused into spatial-attn logits ----
    {
        const int j = tid;
        float acc[NP];
#pragma unroll
        for (int n = 0; n < NP; n++) acc[n] = 0.f;
        const float4* wrow = (const float4*)(w_v2 + (size_t)j * VDIM);
        for (int c4 = 0; c4 < VDIM / 4; c4++){
            float4 w = wrow[c4];
#pragma unroll
            for (int n = 0; n < NP; n++){
                float4 x = ((const float4*)(sR + n * VDIM))[c4];
                acc[n] = fmaf(x.x, w.x, fmaf(x.y, w.y, fmaf(x.z, w.z, fmaf(x.w, w.w, acc[n]))));
            }
        }
        const float bj = b_v2[j];
        const float scale = aq2[j] * w_sa[j];
#pragma unroll
        for (int n = 0; n < NP; n++){
            float v = fmaxf(acc[n] + bj, 0.f) * scale;
            v = wsum(v);
            if ((tid & 31) == 0) atomicAdd(&sSp[n], v);
        }
    }
    __syncthreads();

    // ---- P8: sp_maps = softmax(tanh(logits)) ----
    if (tid < 32){
        float v0 = tanhf(sSp[tid]);
        float v1 = (tid + 32 < NP) ? tanhf(sSp[tid + 32]) : -1e30f;
        float mx = wmax(fmaxf(v0, v1));
        float e0 = expf(v0 - mx);
        float e1 = (tid + 32 < NP) ? expf(v1 - mx) : 0.f;
        float s  = wsum(e0 + e1);
        sSp[tid] = e0 / s;
        if (tid + 32 < NP) sSp[tid + 32] = e1 / s;
    }
    __syncthreads();

    // ---- P9: outputs ----
    for (int p = 0; p < 2; p++){
        int c = tid + p * 256;
        float sa = 0.f, cs = 0.f;
        for (int n = 0; n < NP; n++){
            sa = fmaf(sSelf[n], sV[n * VDIM + c], sa);
            cs = fmaf(sSp[n],   sR[n * VDIM + c], cs);
        }
        float g = 1.f + 0.5f / (1.f + expf(-sa));
        out[(size_t)item * VDIM + c] = cs * g;
    }
    if (tid < ADIM)
        out[(size_t)BT * VDIM + (size_t)item * ADIM + tid] = aud[tid];
}

// ---------------------------------------------------------------------------
extern "C" void kernel_launch(void* const* d_in, const int* in_sizes, int n_in,
                              void* d_out, int out_size)
{
    const float* video = (const float*)d_in[0];
    const float* audio = (const float*)d_in[1];
    const float* wq    = (const float*)d_in[2];  const float* bq    = (const float*)d_in[3];
    const float* wk    = (const float*)d_in[4];  const float* bk    = (const float*)d_in[5];
    const float* wv    = (const float*)d_in[6];  const float* bv    = (const float*)d_in[7];
    const float* ln_g  = (const float*)d_in[8];  const float* ln_b  = (const float*)d_in[9];
    const float* w_ave = (const float*)d_in[10]; const float* b_ave = (const float*)d_in[11];
    const float* w_v3  = (const float*)d_in[12]; const float* b_v3  = (const float*)d_in[13];
    const float* w_avt = (const float*)d_in[14]; const float* b_avt = (const float*)d_in[15];
    const float* w_a1  = (const float*)d_in[16]; const float* b_a1  = (const float*)d_in[17];
    const float* w_v1  = (const float*)d_in[18]; const float* b_v1  = (const float*)d_in[19];
    const float* w_bn  = (const float*)d_in[20]; const float* b_bn  = (const float*)d_in[21];
    const float* w_ca  = (const float*)d_in[22]; const float* b_ca  = (const float*)d_in[23];
    const float* w_v2  = (const float*)d_in[24]; const float* b_v2  = (const float*)d_in[25];
    const float* w_a2  = (const float*)d_in[26]; const float* b_a2  = (const float*)d_in[27];
    const float* w_sa  = (const float*)d_in[28]; const float* b_sa  = (const float*)d_in[29];
    float* out = (float*)d_out;

    const int smem1 = (NP * VDIM * 2 + NP * 52) * (int)sizeof(float);   // ~211 KB
    const int smem2 = (NP * VDIM * 2 + 3072) * (int)sizeof(float);      // ~213 KB
    cudaFuncSetAttribute(k1, cudaFuncAttributeMaxDynamicSharedMemorySize, smem1);
    cudaFuncSetAttribute(k2, cudaFuncAttributeMaxDynamicSharedMemorySize, smem2);

    k1<<<BT, 256, smem1>>>(video, wq, bq, wk, bk, wv, bv, ln_g, ln_b);
    k2<<<BT, 256, smem2>>>(video, audio, w_ave, b_ave, w_v3, b_v3, w_avt, b_avt,
                           w_a1, b_a1, w_v1, b_v1, w_bn, b_bn, w_ca, b_ca,
                           w_v2, b_v2, w_a2, b_a2, w_sa, b_sa, out);
}

// round 5
// speedup vs baseline: 3.3821x; 3.3793x over previous
#include <cuda_runtime.h>
#include <cuda_fp16.h>
#include <math.h>

#define NB 256
#define NT 10
#define BT 2560
#define NP 49
#define VDIM 512
#define HDIM 256
#define ADIM 128
#define LDAH 528
#define LDQK 133
#define LDATT 80

static __device__ float  g_vf2[(size_t)BT * NP * VDIM];
static __device__ __half g_wph[917504];

#define OFF_QK  0
#define OFF_WV  131072
#define OFF_V31 393216
#define OFF_V2  786432

__device__ __forceinline__ float wsum(float v){
#pragma unroll
    for (int s = 16; s > 0; s >>= 1) v += __shfl_xor_sync(0xffffffffu, v, s);
    return v;
}
__device__ __forceinline__ float wmax(float v){
#pragma unroll
    for (int s = 16; s > 0; s >>= 1) v = fmaxf(v, __shfl_xor_sync(0xffffffffu, v, s));
    return v;
}
// permuted k position inside a row so A fragments are contiguous LDS.64
__device__ __forceinline__ int posk(int k){
    int b = k & 15;
    return (k & ~15) + 4*((b & 7) >> 1) + 2*(b >> 3) + (b & 1);
}
__device__ __forceinline__ void mma16(float (&d)[4], unsigned a0, unsigned a1,
                                      unsigned a2, unsigned a3, unsigned b0, unsigned b1){
    asm volatile("mma.sync.aligned.m16n8k16.row.col.f32.f16.f16.f32 "
        "{%0,%1,%2,%3},{%4,%5,%6,%7},{%8,%9},{%0,%1,%2,%3};"
        : "+f"(d[0]), "+f"(d[1]), "+f"(d[2]), "+f"(d[3])
        : "r"(a0), "r"(a1), "r"(a2), "r"(a3), "r"(b0), "r"(b1));
}

// Warp computes C[64 x 32] tile: cols [colbase + warp*32, +32), K = KH.
// A: smem halves, permuted-k layout, ldah stride. B: packed fragment layout.
// acc element (h,i) of a[mt][4]: row = mt*16 + h*8 + g, col = col8 + 2t + i.
template<class E>
__device__ __forceinline__ void gemm_pass(const __half* __restrict__ A, int ldah,
                                          const __half* __restrict__ B, int KH,
                                          int colbase, E epi)
{
    const int lane = threadIdx.x & 31, warp = threadIdx.x >> 5;
    const int g = lane >> 2, t = lane & 3;
    const int col0 = colbase + warp * 32;
    const int ntb = col0 >> 3;
    const int nk32 = KH >> 5;
    float acc[4][4][4];
#pragma unroll
    for (int nt = 0; nt < 4; nt++)
#pragma unroll
    for (int mt = 0; mt < 4; mt++)
#pragma unroll
    for (int i = 0; i < 4; i++) acc[nt][mt][i] = 0.f;

    for (int k32 = 0; k32 < nk32; k32++){
        uint4 bv[4];
#pragma unroll
        for (int nt = 0; nt < 4; nt++)
            bv[nt] = *(const uint4*)(B + ((size_t)((ntb+nt)*nk32 + k32)*32 + lane)*8);
#pragma unroll
        for (int s = 0; s < 2; s++){
            const int k0 = k32*32 + s*16 + 4*t;
            unsigned a0[4], a1[4], a2[4], a3[4];
#pragma unroll
            for (int mt = 0; mt < 4; mt++){
                uint2 lo = *(const uint2*)(A + (mt*16 +     g)*ldah + k0);
                uint2 hi = *(const uint2*)(A + (mt*16 + 8 + g)*ldah + k0);
                a0[mt] = lo.x; a2[mt] = lo.y; a1[mt] = hi.x; a3[mt] = hi.y;
            }
#pragma unroll
            for (int nt = 0; nt < 4; nt++){
                unsigned b0 = s ? bv[nt].z : bv[nt].x;
                unsigned b1 = s ? bv[nt].w : bv[nt].y;
#pragma unroll
                for (int mt = 0; mt < 4; mt++)
                    mma16(acc[nt][mt], a0[mt], a1[mt], a2[mt], a3[mt], b0, b1);
            }
        }
    }
#pragma unroll
    for (int nt = 0; nt < 4; nt++) epi(col0 + nt*8, acc[nt]);
}

// coalesced warp-per-row GEMV (fp32 weights from global)
template<int K, class F>
__device__ __forceinline__ void gemv8(const float* __restrict__ W,
                                      const float* __restrict__ x, int N, F f){
    const int lane = threadIdx.x & 31, warp = threadIdx.x >> 5;
    for (int j = warp; j < N; j += 8){
        const float4* wr = (const float4*)(W + (size_t)j * K);
        float s = 0.f;
#pragma unroll
        for (int c = 0; c < K/128; c++){
            float4 a = __ldg(wr + lane + 32*c);
            float4 b = ((const float4*)x)[lane + 32*c];
            s = fmaf(a.x,b.x, fmaf(a.y,b.y, fmaf(a.z,b.z, fmaf(a.w,b.w, s))));
        }
        s = wsum(s);
        if (lane == 0) f(j, s);
    }
}

// ---- weight repack: W[N x 512] fp32 -> fragment-packed fp16 ----
__global__ void repack(const float* __restrict__ src, __half* __restrict__ dst, int N){
    int total = N * 512;
    for (int i = blockIdx.x*blockDim.x + threadIdx.x; i < total; i += gridDim.x*blockDim.x){
        int h = i & 7, r = i >> 3;
        int lane = r & 31; r >>= 5;
        int k32 = r & 15;  int nt = r >> 4;
        int g = lane >> 2, t = lane & 3;
        int s = h >> 2, hi = (h >> 1) & 1, lo = h & 1;
        int n = nt*8 + g;
        int k = k32*32 + 16*s + 8*hi + 2*t + lo;
        dst[i] = __float2half(src[(size_t)n*512 + k]);
    }
}

// ---------------------------------------------------------------------------
// Kernel 1: self-attention; writes pre-LN (vf + out) to g_vf2
// ---------------------------------------------------------------------------
__global__ void __launch_bounds__(256, 1)
k1(const float* __restrict__ video, const float* __restrict__ bq,
   const float* __restrict__ bk, const float* __restrict__ bv)
{
    extern __shared__ __align__(16) unsigned char smraw[];
    __half* sA   = (__half*)smraw;                       // 64*528 h = 67584B
    float*  sQ   = (float*)(smraw + 67584);              // 64*133 f
    float*  sK   = sQ + 64*LDQK;                         // 64*133 f (ends 135680)
    __half* sZp  = (__half*)(smraw + 67584);             // overlays sQ/sK after softmax
    __half* sAtt = (__half*)(smraw + 135680);            // 64*80 h = 10240B

    const int tid = threadIdx.x, lane = tid & 31, warp = tid >> 5;
    const int g = lane >> 2, t = lane & 3;
    const int item = blockIdx.x;
    const float* vf = video + (size_t)item * NP * VDIM;

    // load X (fp16, permuted), zero pads
    for (int i = tid; i < NP*VDIM; i += 256)
        sA[(i >> 9)*LDAH + posk(i & 511)] = __float2half(vf[i]);
    for (int i = tid; i < 15*LDAH; i += 256) sA[49*LDAH + i] = __float2half(0.f);
    for (int i = tid; i < 64*LDATT; i += 256) sAtt[i] = __float2half(0.f);
    __syncthreads();

    // ---- q|k GEMM (N=256) ----
    gemm_pass(sA, LDAH, g_wph + OFF_QK, 512, 0,
        [&](int col8, float (&a)[4][4]){
            int c0 = col8 + 2*t;
            float* d0; float bb0, bb1;
            if (c0 < 128){ d0 = sQ + c0;       bb0 = bq[c0];     bb1 = bq[c0+1]; }
            else         { d0 = sK + c0 - 128; bb0 = bk[c0-128]; bb1 = bk[c0-127]; }
#pragma unroll
            for (int mt = 0; mt < 4; mt++)
#pragma unroll
            for (int h = 0; h < 2; h++){
                int r = mt*16 + h*8 + g;
                d0[r*LDQK]     = a[mt][h*2]   + bb0;
                d0[r*LDQK + 1] = a[mt][h*2+1] + bb1;
            }
        });
    __syncthreads();

    // ---- softmax(q k^T), warp per row, write fp16 permuted attn ----
    for (int n = warp; n < NP; n += 8){
        float a0 = 0.f, a1 = 0.f;
        const int m1 = lane + 32;
        const int m1c = (m1 < NP) ? m1 : 0;
        for (int j = 0; j < 128; j++){
            float q = sQ[n*LDQK + j];
            a0 = fmaf(q, sK[lane*LDQK + j], a0);
            a1 = fmaf(q, sK[m1c *LDQK + j], a1);
        }
        float v1 = (m1 < NP) ? a1 : -1e30f;
        float mx = wmax(fmaxf(a0, v1));
        float e0 = expf(a0 - mx);
        float e1 = (m1 < NP) ? expf(a1 - mx) : 0.f;
        float s = wsum(e0 + e1);
        float inv = 1.f / s;
        sAtt[n*LDATT + posk(lane)] = __float2half(e0 * inv);
        if (m1 < NP) sAtt[n*LDATT + posk(m1)] = __float2half(e1 * inv);
    }
    __syncthreads();

    // ---- Z = X @ Wv^T, written in packed-B layout (overlays dead q/k) ----
    for (int pass = 0; pass < 2; pass++)
        gemm_pass(sA, LDAH, g_wph + OFF_WV, 512, pass*256,
            [&](int col8, float (&a)[4][4]){
#pragma unroll
                for (int mt = 0; mt < 4; mt++)
#pragma unroll
                for (int h = 0; h < 2; h++)
#pragma unroll
                for (int i = 0; i < 2; i++){
                    int m = mt*16 + h*8 + g;
                    int col = col8 + 2*t + i;
                    int k32 = m >> 5, b = m & 31;
                    int s = b >> 4, rem = b & 15;
                    int hi = rem >> 3, tp = (rem >> 1) & 3, lo = rem & 1;
                    int off = (((col >> 3)*2 + k32)*32 + ((col & 7)*4 + tp))*8
                              + s*4 + hi*2 + lo;
                    sZp[off] = __float2half(a[mt][h*2 + i]);
                }
            });
    __syncthreads();

    // ---- out = attn @ Z + bv + video  -> g_vf2 (pre-LN) ----
    float* gv = g_vf2 + (size_t)item * NP * VDIM;
    for (int pass = 0; pass < 2; pass++)
        gemm_pass(sAtt, LDATT, sZp, 64, pass*256,
            [&](int col8, float (&a)[4][4]){
#pragma unroll
                for (int mt = 0; mt < 4; mt++)
#pragma unroll
                for (int h = 0; h < 2; h++){
                    int n = mt*16 + h*8 + g;
                    if (n < NP){
#pragma unroll
                        for (int i = 0; i < 2; i++){
                            int col = col8 + 2*t + i;
                            gv[n*VDIM + col] = a[mt][h*2+i] + bv[col] + vf[n*VDIM + col];
                        }
                    }
                }
            });
}

// ---------------------------------------------------------------------------
// Kernel 2: LN + all audio-guided branches
// ---------------------------------------------------------------------------
__global__ void __launch_bounds__(256)
k2(const float* __restrict__ video, const float* __restrict__ audio,
   const float* __restrict__ ln_g, const float* __restrict__ ln_b,
   const float* __restrict__ b_ave, const float* __restrict__ b_v3,
   const float* __restrict__ w_avatt, const float* __restrict__ b_avatt,
   const float* __restrict__ b_a1, const float* __restrict__ b_v1,
   const float* __restrict__ b_bn, const float* __restrict__ b_ca,
   const float* __restrict__ b_v2, const float* __restrict__ b_a2,
   const float* __restrict__ w_sa, const float* __restrict__ b_sa,
   const float* __restrict__ w_ave, const float* __restrict__ w_a1,
   const float* __restrict__ w_bn, const float* __restrict__ w_ca,
   const float* __restrict__ w_a2,
   float* __restrict__ out)
{
    extern __shared__ __align__(16) unsigned char smraw[];
    __half* sA   = (__half*)smraw;              // 64*528 h = 67584B
    float*  fb   = (float*)(smraw + 67584);
    float* colm = fb;        float* aq1  = fb + 512;
    float* ch   = fb + 1024; float* colv = fb + 1536;
    float* sav  = fb + 2048; float* havg = fb + 2560;
    float* aq2  = fb + 2816; float* avqv = fb + 3072;
    float* aud  = fb + 3328; float* sSelf= fb + 3456;
    float* sSp  = fb + 3520;

    const int tid = threadIdx.x, lane = tid & 31, warp = tid >> 5;
    const int g = lane >> 2, t = lane & 3;
    const int item = blockIdx.x;
    const int bb = item / NT, tt = item % NT;
    const float* vf = video + (size_t)item * NP * VDIM;
    const float* gv = g_vf2 + (size_t)item * NP * VDIM;

    // ---- P0: LayerNorm rows of g_vf2 -> sA fp16 permuted ----
    for (int n = warp; n < NP; n += 8){
        const float* src = gv + n*VDIM;
        float s = 0.f, s2 = 0.f;
        for (int j = lane; j < VDIM; j += 32){
            float v = src[j]; s += v; s2 = fmaf(v, v, s2);
        }
        s = wsum(s); s2 = wsum(s2);
        float mu = s * (1.f/VDIM);
        float var = s2 * (1.f/VDIM) - mu*mu;
        float rs = rsqrtf(var + 1e-5f);
        for (int j = lane; j < VDIM; j += 32){
            float v = (src[j] - mu) * rs * ln_g[j] + ln_b[j];
            sA[n*LDAH + posk(j)] = __float2half(v);
        }
    }
    for (int i = tid; i < 15*LDAH; i += 256) sA[49*LDAH + i] = __float2half(0.f);
    {
        const float* ap = audio + ((size_t)tt * NB + bb) * ADIM;
        if (tid < ADIM) aud[tid] = ap[tid];
        if (tid < 64){ sSelf[tid] = (tid < NP) ? b_avatt[0] : 0.f;
                       sSp[tid]   = (tid < NP) ? b_sa[0]   : 0.f; }
    }
    __syncthreads();

    // ---- P1: colm, aq1, aq2 ----
    for (int p = 0; p < 2; p++){
        int c = tid + p*256; int pc = posk(c);
        float s = 0.f;
        for (int n = 0; n < NP; n++) s += __half2float(sA[n*LDAH + pc]);
        colm[c] = s * (1.f/NP);
    }
    gemv8<ADIM>(w_a1, aud, 512, [&](int j, float s){ aq1[j] = fmaxf(s + b_a1[j], 0.f); });
    gemv8<ADIM>(w_a2, aud, 256, [&](int j, float s){ aq2[j] = fmaxf(s + b_a2[j], 0.f); });
    __syncthreads();

    // ---- P2: havg ----
    gemv8<VDIM>(w_ave, colm, 256, [&](int j, float s){ havg[j] = fmaxf(s + b_ave[j], 0.f); });
    __syncthreads();

    // ---- P3: combined [w_v3 | w_v1] GEMM (N=768) ----
    for (int pass = 0; pass < 3; pass++)
        gemm_pass(sA, LDAH, g_wph + OFF_V31, 512, pass*256,
            [&](int col8, float (&a)[4][4]){
                int c0 = col8 + 2*t;
                if (col8 < 256){  // w_v3 -> self logits
                    float s0 = havg[c0]   * w_avatt[c0];
                    float s1 = havg[c0+1] * w_avatt[c0+1];
                    float bb0 = b_v3[c0], bb1 = b_v3[c0+1];
#pragma unroll
                    for (int mt = 0; mt < 4; mt++)
#pragma unroll
                    for (int h = 0; h < 2; h++){
                        int r = mt*16 + h*8 + g;
                        float v = fmaxf(a[mt][h*2]+bb0,0.f)*s0 + fmaxf(a[mt][h*2+1]+bb1,0.f)*s1;
                        v += __shfl_xor_sync(0xffffffffu, v, 1);
                        v += __shfl_xor_sync(0xffffffffu, v, 2);
                        if (t == 0 && r < NP) atomicAdd(&sSelf[r], v);
                    }
                } else {          // w_v1 -> colv
                    int c = c0 - 256;
                    float bb0 = b_v1[c], bb1 = b_v1[c+1];
                    float s0 = 0.f, s1 = 0.f;
#pragma unroll
                    for (int mt = 0; mt < 4; mt++)
#pragma unroll
                    for (int h = 0; h < 2; h++){
                        int r = mt*16 + h*8 + g;
                        if (r < NP){
                            s0 += fmaxf(a[mt][h*2]   + bb0, 0.f);
                            s1 += fmaxf(a[mt][h*2+1] + bb1, 0.f);
                        }
                    }
                    s0 += __shfl_xor_sync(0xffffffffu, s0, 4);
                    s0 += __shfl_xor_sync(0xffffffffu, s0, 8);
                    s0 += __shfl_xor_sync(0xffffffffu, s0, 16);
                    s1 += __shfl_xor_sync(0xffffffffu, s1, 4);
                    s1 += __shfl_xor_sync(0xffffffffu, s1, 8);
                    s1 += __shfl_xor_sync(0xffffffffu, s1, 16);
                    if (g == 0){
                        colv[c]   = s0 * (1.f/NP) * aq1[c];
                        colv[c+1] = s1 * (1.f/NP) * aq1[c+1];
                    }
                }
            });
    __syncthreads();

    // ---- P4: self softmax; avq ----
    if (tid < 32){
        float v0 = tanhf(sSelf[tid]);
        float v1 = (tid + 32 < NP) ? tanhf(sSelf[tid+32]) : -1e30f;
        float mx = wmax(fmaxf(v0, v1));
        float e0 = expf(v0 - mx);
        float e1 = (tid + 32 < NP) ? expf(v1 - mx) : 0.f;
        float s = wsum(e0 + e1);
        sSelf[tid] = e0 / s;
        if (tid + 32 < NP) sSelf[tid+32] = e1 / s;
    }
    gemv8<VDIM>(w_bn, colv, 256, [&](int j, float s){ avqv[j] = fmaxf(s + b_bn[j], 0.f); });
    __syncthreads();

    // ---- P5: sa = self_maps @ vf2 ; ch = 1 + sigmoid(W_ca avq) ----
    for (int p = 0; p < 2; p++){
        int c = tid + p*256; int pc = posk(c);
        float s = 0.f;
        for (int n = 0; n < NP; n++)
            s = fmaf(sSelf[n], __half2float(sA[n*LDAH + pc]), s);
        sav[c] = s;
    }
    gemv8<HDIM>(w_ca, avqv, 512, [&](int j, float s){
        ch[j] = 1.f + 1.f/(1.f + expf(-(s + b_ca[j])));
    });
    __syncthreads();

    // ---- P6: overwrite sA with c_att = video * ch ----
    for (int i = tid; i < NP*VDIM; i += 256){
        int c = i & 511;
        sA[(i >> 9)*LDAH + posk(c)] = __float2half(vf[i] * ch[c]);
    }
    __syncthreads();

    // ---- P7: w_v2 GEMM -> spatial logits (N=256) ----
    gemm_pass(sA, LDAH, g_wph + OFF_V2, 512, 0,
        [&](int col8, float (&a)[4][4]){
            int c0 = col8 + 2*t;
            float s0 = aq2[c0]   * w_sa[c0];
            float s1 = aq2[c0+1] * w_sa[c0+1];
            float bb0 = b_v2[c0], bb1 = b_v2[c0+1];
#pragma unroll
            for (int mt = 0; mt < 4; mt++)
#pragma unroll
            for (int h = 0; h < 2; h++){
                int r = mt*16 + h*8 + g;
                float v = fmaxf(a[mt][h*2]+bb0,0.f)*s0 + fmaxf(a[mt][h*2+1]+bb1,0.f)*s1;
                v += __shfl_xor_sync(0xffffffffu, v, 1);
                v += __shfl_xor_sync(0xffffffffu, v, 2);
                if (t == 0 && r < NP) atomicAdd(&sSp[r], v);
            }
        });
    __syncthreads();

    // ---- P8: spatial softmax ----
    if (tid < 32){
        float v0 = tanhf(sSp[tid]);
        float v1 = (tid + 32 < NP) ? tanhf(sSp[tid+32]) : -1e30f;
        float mx = wmax(fmaxf(v0, v1));
        float e0 = expf(v0 - mx);
        float e1 = (tid + 32 < NP) ? expf(v1 - mx) : 0.f;
        float s = wsum(e0 + e1);
        sSp[tid] = e0 / s;
        if (tid + 32 < NP) sSp[tid+32] = e1 / s;
    }
    __syncthreads();

    // ---- P9: outputs ----
    for (int p = 0; p < 2; p++){
        int c = tid + p*256; int pc = posk(c);
        float cs = 0.f;
        for (int n = 0; n < NP; n++)
            cs = fmaf(sSp[n], __half2float(sA[n*LDAH + pc]), cs);
        float gate = 1.f + 0.5f/(1.f + expf(-sav[c]));
        out[(size_t)item*VDIM + c] = cs * gate;
    }
    if (tid < ADIM)
        out[(size_t)BT*VDIM + (size_t)item*ADIM + tid] = aud[tid];
}

// ---------------------------------------------------------------------------
extern "C" void kernel_launch(void* const* d_in, const int* in_sizes, int n_in,
                              void* d_out, int out_size)
{
    const float* video = (const float*)d_in[0];
    const float* audio = (const float*)d_in[1];
    const float* wq    = (const float*)d_in[2];  const float* bq    = (const float*)d_in[3];
    const float* wk    = (const float*)d_in[4];  const float* bk    = (const float*)d_in[5];
    const float* wv    = (const float*)d_in[6];  const float* bv    = (const float*)d_in[7];
    const float* ln_g  = (const float*)d_in[8];  const float* ln_b  = (const float*)d_in[9];
    const float* w_ave = (const float*)d_in[10]; const float* b_ave = (const float*)d_in[11];
    const float* w_v3  = (const float*)d_in[12]; const float* b_v3  = (const float*)d_in[13];
    const float* w_avt = (const float*)d_in[14]; const float* b_avt = (const float*)d_in[15];
    const float* w_a1  = (const float*)d_in[16]; const float* b_a1  = (const float*)d_in[17];
    const float* w_v1  = (const float*)d_in[18]; const float* b_v1  = (const float*)d_in[19];
    const float* w_bn  = (const float*)d_in[20]; const float* b_bn  = (const float*)d_in[21];
    const float* w_ca  = (const float*)d_in[22]; const float* b_ca  = (const float*)d_in[23];
    const float* w_v2  = (const float*)d_in[24]; const float* b_v2  = (const float*)d_in[25];
    const float* w_a2  = (const float*)d_in[26]; const float* b_a2  = (const float*)d_in[27];
    const float* w_sa  = (const float*)d_in[28]; const float* b_sa  = (const float*)d_in[29];
    float* out = (float*)d_out;

    __half* wph = nullptr;
    cudaGetSymbolAddress((void**)&wph, g_wph);

    repack<<<128, 256>>>(wq,   wph + OFF_QK,           128);
    repack<<<128, 256>>>(wk,   wph + OFF_QK + 65536,   128);
    repack<<<256, 256>>>(wv,   wph + OFF_WV,           512);
    repack<<<128, 256>>>(w_v3, wph + OFF_V31,          256);
    repack<<<256, 256>>>(w_v1, wph + OFF_V31 + 131072, 512);
    repack<<<128, 256>>>(w_v2, wph + OFF_V2,           256);

    const int smem1 = 145920;
    const int smem2 = 81920;
    cudaFuncSetAttribute(k1, cudaFuncAttributeMaxDynamicSharedMemorySize, smem1);
    cudaFuncSetAttribute(k2, cudaFuncAttributeMaxDynamicSharedMemorySize, smem2);

    k1<<<BT, 256, smem1>>>(video, bq, bk, bv);
    k2<<<BT, 256, smem2>>>(video, audio, ln_g, ln_b, b_ave, b_v3, w_avt, b_avt,
                           b_a1, b_v1, b_bn, b_ca, b_v2, b_a2, w_sa, b_sa,
                           w_ave, w_a1, w_bn, w_ca, w_a2, out);
}

// round 6
// speedup vs baseline: 3.4473x; 1.0193x over previous
#include <cuda_runtime.h>
#include <cuda_fp16.h>
#include <math.h>

#define NB 256
#define NT 10
#define BT 2560
#define NP 49
#define VDIM 512
#define HDIM 256
#define ADIM 128
#define LDAH 528
#define LDQK 133
#define LDATT 80

static __device__ float  g_vf2[(size_t)BT * NP * VDIM];
static __device__ __half g_wph[917504];

#define OFF_QK  0
#define OFF_WV  131072
#define OFF_V31 393216
#define OFF_V2  786432

__device__ __forceinline__ float wsum(float v){
#pragma unroll
    for (int s = 16; s > 0; s >>= 1) v += __shfl_xor_sync(0xffffffffu, v, s);
    return v;
}
__device__ __forceinline__ float wmax(float v){
#pragma unroll
    for (int s = 16; s > 0; s >>= 1) v = fmaxf(v, __shfl_xor_sync(0xffffffffu, v, s));
    return v;
}
// permuted k position inside a row so A fragments are contiguous LDS.64
__device__ __forceinline__ int posk(int k){
    int b = k & 15;
    return (k & ~15) + 4*((b & 7) >> 1) + 2*(b >> 3) + (b & 1);
}
__device__ __forceinline__ void mma16(float (&d)[4], unsigned a0, unsigned a1,
                                      unsigned a2, unsigned a3, unsigned b0, unsigned b1){
    asm volatile("mma.sync.aligned.m16n8k16.row.col.f32.f16.f16.f32 "
        "{%0,%1,%2,%3},{%4,%5,%6,%7},{%8,%9},{%0,%1,%2,%3};"
        : "+f"(d[0]), "+f"(d[1]), "+f"(d[2]), "+f"(d[3])
        : "r"(a0), "r"(a1), "r"(a2), "r"(a3), "r"(b0), "r"(b1));
}

// Warp computes C[64 x 32] tile: cols [colbase + warp*32, +32), K = KH (compile time).
// A: smem halves, permuted-k layout. B: packed fragment layout (global/L2 or smem).
// Manual 1-deep prefetch of B fragments hides L2 latency.
template<int KH, class E>
__device__ __forceinline__ void gemm_pass(const __half* __restrict__ A, int ldah,
                                          const __half* __restrict__ B,
                                          int colbase, E epi)
{
    const int lane = threadIdx.x & 31, warp = threadIdx.x >> 5;
    const int g = lane >> 2, t = lane & 3;
    const int col0 = colbase + warp * 32;
    const int ntb = col0 >> 3;
    constexpr int nk32 = KH >> 5;
    float acc[4][4][4];
#pragma unroll
    for (int nt = 0; nt < 4; nt++)
#pragma unroll
    for (int mt = 0; mt < 4; mt++)
#pragma unroll
    for (int i = 0; i < 4; i++) acc[nt][mt][i] = 0.f;

    const __half* Bp = B + (size_t)ntb * nk32 * 256 + lane * 8;
    uint4 bv[4];
#pragma unroll
    for (int nt = 0; nt < 4; nt++)
        bv[nt] = *(const uint4*)(Bp + (size_t)nt * nk32 * 256);

#pragma unroll 2
    for (int k32 = 0; k32 < nk32; k32++){
        uint4 bn[4];
        if (k32 + 1 < nk32){
#pragma unroll
            for (int nt = 0; nt < 4; nt++)
                bn[nt] = *(const uint4*)(Bp + ((size_t)nt * nk32 + k32 + 1) * 256);
        }
#pragma unroll
        for (int s = 0; s < 2; s++){
            const int k0 = k32*32 + s*16 + 4*t;
            unsigned a0[4], a1[4], a2[4], a3[4];
#pragma unroll
            for (int mt = 0; mt < 4; mt++){
                uint2 lo = *(const uint2*)(A + (mt*16 +     g)*ldah + k0);
                uint2 hi = *(const uint2*)(A + (mt*16 + 8 + g)*ldah + k0);
                a0[mt] = lo.x; a2[mt] = lo.y; a1[mt] = hi.x; a3[mt] = hi.y;
            }
#pragma unroll
            for (int nt = 0; nt < 4; nt++){
                unsigned b0 = s ? bv[nt].z : bv[nt].x;
                unsigned b1 = s ? bv[nt].w : bv[nt].y;
#pragma unroll
                for (int mt = 0; mt < 4; mt++)
                    mma16(acc[nt][mt], a0[mt], a1[mt], a2[mt], a3[mt], b0, b1);
            }
        }
#pragma unroll
        for (int nt = 0; nt < 4; nt++) bv[nt] = bn[nt];
    }
#pragma unroll
    for (int nt = 0; nt < 4; nt++) epi(col0 + nt*8, acc[nt]);
}

// coalesced warp-per-row GEMV (fp32 weights from global)
template<int K, class F>
__device__ __forceinline__ void gemv8(const float* __restrict__ W,
                                      const float* __restrict__ x, int N, F f){
    const int lane = threadIdx.x & 31, warp = threadIdx.x >> 5;
    for (int j = warp; j < N; j += 8){
        const float4* wr = (const float4*)(W + (size_t)j * K);
        float s = 0.f;
#pragma unroll
        for (int c = 0; c < K/128; c++){
            float4 a = __ldg(wr + lane + 32*c);
            float4 b = ((const float4*)x)[lane + 32*c];
            s = fmaf(a.x,b.x, fmaf(a.y,b.y, fmaf(a.z,b.z, fmaf(a.w,b.w, s))));
        }
        s = wsum(s);
        if (lane == 0) f(j, s);
    }
}

// ---- single fused weight repack: all six matrices -> fragment-packed fp16 ----
__global__ void repack_all(const float* __restrict__ wq, const float* __restrict__ wk,
                           const float* __restrict__ wv, const float* __restrict__ w_v3,
                           const float* __restrict__ w_v1, const float* __restrict__ w_v2)
{
    int i = blockIdx.x*blockDim.x + threadIdx.x;
    if (i >= 917504) return;
    const float* src; int base;
    if      (i < 65536)  { src = wq;   base = 0; }
    else if (i < 131072) { src = wk;   base = 65536; }
    else if (i < 393216) { src = wv;   base = 131072; }
    else if (i < 524288) { src = w_v3; base = 393216; }
    else if (i < 786432) { src = w_v1; base = 524288; }
    else                 { src = w_v2; base = 786432; }
    int li = i - base;
    int h = li & 7, r = li >> 3;
    int lane = r & 31; r >>= 5;
    int k32 = r & 15;  int nt = r >> 4;
    int g = lane >> 2, t = lane & 3;
    int s = h >> 2, hi = (h >> 1) & 1, lo = h & 1;
    int n = nt*8 + g;
    int k = k32*32 + 16*s + 8*hi + 2*t + lo;
    g_wph[i] = __float2half(src[(size_t)n*512 + k]);
}

// ---------------------------------------------------------------------------
// Kernel 1: self-attention; writes pre-LN (vf + out) to g_vf2
// ---------------------------------------------------------------------------
__global__ void __launch_bounds__(256, 1)
k1(const float* __restrict__ video, const float* __restrict__ bq,
   const float* __restrict__ bk, const float* __restrict__ bv)
{
    extern __shared__ __align__(16) unsigned char smraw[];
    __half* sA   = (__half*)smraw;                       // 64*528 h = 67584B
    float*  sQ   = (float*)(smraw + 67584);              // 64*133 f
    float*  sK   = sQ + 64*LDQK;                         // 64*133 f (ends 135680)
    __half* sZp  = (__half*)(smraw + 67584);             // overlays sQ/sK after softmax
    __half* sAtt = (__half*)(smraw + 135680);            // 64*80 h = 10240B

    const int tid = threadIdx.x, lane = tid & 31, warp = tid >> 5;
    const int g = lane >> 2, t = lane & 3;
    const int item = blockIdx.x;
    const float* vf = video + (size_t)item * NP * VDIM;

    // load X (fp16, permuted), zero pads
    for (int i = tid; i < NP*VDIM; i += 256)
        sA[(i >> 9)*LDAH + posk(i & 511)] = __float2half(vf[i]);
    for (int i = tid; i < 15*LDAH; i += 256) sA[49*LDAH + i] = __float2half(0.f);
    for (int i = tid; i < 64*LDATT; i += 256) sAtt[i] = __float2half(0.f);
    __syncthreads();

    // ---- q|k GEMM (N=256) ----
    gemm_pass<512>(sA, LDAH, g_wph + OFF_QK, 0,
        [&](int col8, float (&a)[4][4]){
            int c0 = col8 + 2*t;
            float* d0; float bb0, bb1;
            if (c0 < 128){ d0 = sQ + c0;       bb0 = bq[c0];     bb1 = bq[c0+1]; }
            else         { d0 = sK + c0 - 128; bb0 = bk[c0-128]; bb1 = bk[c0-127]; }
#pragma unroll
            for (int mt = 0; mt < 4; mt++)
#pragma unroll
            for (int h = 0; h < 2; h++){
                int r = mt*16 + h*8 + g;
                d0[r*LDQK]     = a[mt][h*2]   + bb0;
                d0[r*LDQK + 1] = a[mt][h*2+1] + bb1;
            }
        });
    __syncthreads();

    // ---- softmax(q k^T), warp per row, write fp16 permuted attn ----
    for (int n = warp; n < NP; n += 8){
        float a0 = 0.f, a1 = 0.f;
        const int m1 = lane + 32;
        const int m1c = (m1 < NP) ? m1 : 0;
        for (int j = 0; j < 128; j++){
            float q = sQ[n*LDQK + j];
            a0 = fmaf(q, sK[lane*LDQK + j], a0);
            a1 = fmaf(q, sK[m1c *LDQK + j], a1);
        }
        float v1 = (m1 < NP) ? a1 : -1e30f;
        float mx = wmax(fmaxf(a0, v1));
        float e0 = expf(a0 - mx);
        float e1 = (m1 < NP) ? expf(a1 - mx) : 0.f;
        float s = wsum(e0 + e1);
        float inv = 1.f / s;
        sAtt[n*LDATT + posk(lane)] = __float2half(e0 * inv);
        if (m1 < NP) sAtt[n*LDATT + posk(m1)] = __float2half(e1 * inv);
    }
    __syncthreads();

    // ---- Z = X @ Wv^T, written in packed-B layout (overlays dead q/k) ----
    for (int pass = 0; pass < 2; pass++)
        gemm_pass<512>(sA, LDAH, g_wph + OFF_WV, pass*256,
            [&](int col8, float (&a)[4][4]){
#pragma unroll
                for (int mt = 0; mt < 4; mt++)
#pragma unroll
                for (int h = 0; h < 2; h++)
#pragma unroll
                for (int i = 0; i < 2; i++){
                    int m = mt*16 + h*8 + g;
                    int col = col8 + 2*t + i;
                    int k32 = m >> 5, b = m & 31;
                    int s = b >> 4, rem = b & 15;
                    int hi = rem >> 3, tp = (rem >> 1) & 3, lo = rem & 1;
                    int off = (((col >> 3)*2 + k32)*32 + ((col & 7)*4 + tp))*8
                              + s*4 + hi*2 + lo;
                    sZp[off] = __float2half(a[mt][h*2 + i]);
                }
            });
    __syncthreads();

    // ---- out = attn @ Z + bv + video  -> g_vf2 (pre-LN) ----
    float* gv = g_vf2 + (size_t)item * NP * VDIM;
    for (int pass = 0; pass < 2; pass++)
        gemm_pass<64>(sAtt, LDATT, sZp, pass*256,
            [&](int col8, float (&a)[4][4]){
#pragma unroll
                for (int mt = 0; mt < 4; mt++)
#pragma unroll
                for (int h = 0; h < 2; h++){
                    int n = mt*16 + h*8 + g;
                    if (n < NP){
#pragma unroll
                        for (int i = 0; i < 2; i++){
                            int col = col8 + 2*t + i;
                            gv[n*VDIM + col] = a[mt][h*2+i] + bv[col] + vf[n*VDIM + col];
                        }
                    }
                }
            });
}

// ---------------------------------------------------------------------------
// Kernel 2: LN + all audio-guided branches
// ---------------------------------------------------------------------------
__global__ void __launch_bounds__(256)
k2(const float* __restrict__ video, const float* __restrict__ audio,
   const float* __restrict__ ln_g, const float* __restrict__ ln_b,
   const float* __restrict__ b_ave, const float* __restrict__ b_v3,
   const float* __restrict__ w_avatt, const float* __restrict__ b_avatt,
   const float* __restrict__ b_a1, const float* __restrict__ b_v1,
   const float* __restrict__ b_bn, const float* __restrict__ b_ca,
   const float* __restrict__ b_v2, const float* __restrict__ b_a2,
   const float* __restrict__ w_sa, const float* __restrict__ b_sa,
   const float* __restrict__ w_ave, const float* __restrict__ w_a1,
   const float* __restrict__ w_bn, const float* __restrict__ w_ca,
   const float* __restrict__ w_a2,
   float* __restrict__ out)
{
    extern __shared__ __align__(16) unsigned char smraw[];
    __half* sA   = (__half*)smraw;              // 64*528 h = 67584B
    float*  fb   = (float*)(smraw + 67584);
    float* colm = fb;        float* aq1  = fb + 512;
    float* ch   = fb + 1024; float* colv = fb + 1536;
    float* sav  = fb + 2048; float* havg = fb + 2560;
    float* aq2  = fb + 2816; float* avqv = fb + 3072;
    float* aud  = fb + 3328; float* sSelf= fb + 3456;
    float* sSp  = fb + 3520;

    const int tid = threadIdx.x, lane = tid & 31, warp = tid >> 5;
    const int g = lane >> 2, t = lane & 3;
    const int item = blockIdx.x;
    const int bb = item / NT, tt = item % NT;
    const float* vf = video + (size_t)item * NP * VDIM;
    const float* gv = g_vf2 + (size_t)item * NP * VDIM;

    // ---- P0: LayerNorm rows of g_vf2 -> sA fp16 permuted ----
    for (int n = warp; n < NP; n += 8){
        const float* src = gv + n*VDIM;
        float s = 0.f, s2 = 0.f;
        for (int j = lane; j < VDIM; j += 32){
            float v = src[j]; s += v; s2 = fmaf(v, v, s2);
        }
        s = wsum(s); s2 = wsum(s2);
        float mu = s * (1.f/VDIM);
        float var = s2 * (1.f/VDIM) - mu*mu;
        float rs = rsqrtf(var + 1e-5f);
        for (int j = lane; j < VDIM; j += 32){
            float v = (src[j] - mu) * rs * ln_g[j] + ln_b[j];
            sA[n*LDAH + posk(j)] = __float2half(v);
        }
    }
    for (int i = tid; i < 15*LDAH; i += 256) sA[49*LDAH + i] = __float2half(0.f);
    {
        const float* ap = audio + ((size_t)tt * NB + bb) * ADIM;
        if (tid < ADIM) aud[tid] = ap[tid];
        if (tid < 64){ sSelf[tid] = (tid < NP) ? b_avatt[0] : 0.f;
                       sSp[tid]   = (tid < NP) ? b_sa[0]   : 0.f; }
    }
    __syncthreads();

    // ---- P1: colm, aq1, aq2 ----
    for (int p = 0; p < 2; p++){
        int c = tid + p*256; int pc = posk(c);
        float s = 0.f;
        for (int n = 0; n < NP; n++) s += __half2float(sA[n*LDAH + pc]);
        colm[c] = s * (1.f/NP);
    }
    gemv8<ADIM>(w_a1, aud, 512, [&](int j, float s){ aq1[j] = fmaxf(s + b_a1[j], 0.f); });
    gemv8<ADIM>(w_a2, aud, 256, [&](int j, float s){ aq2[j] = fmaxf(s + b_a2[j], 0.f); });
    __syncthreads();

    // ---- P2: havg ----
    gemv8<VDIM>(w_ave, colm, 256, [&](int j, float s){ havg[j] = fmaxf(s + b_ave[j], 0.f); });
    __syncthreads();

    // ---- P3: combined [w_v3 | w_v1] GEMM (N=768) ----
    for (int pass = 0; pass < 3; pass++)
        gemm_pass<512>(sA, LDAH, g_wph + OFF_V31, pass*256,
            [&](int col8, float (&a)[4][4]){
                int c0 = col8 + 2*t;
                if (col8 < 256){  // w_v3 -> self logits
                    float s0 = havg[c0]   * w_avatt[c0];
                    float s1 = havg[c0+1] * w_avatt[c0+1];
                    float bb0 = b_v3[c0], bb1 = b_v3[c0+1];
#pragma unroll
                    for (int mt = 0; mt < 4; mt++)
#pragma unroll
                    for (int h = 0; h < 2; h++){
                        int r = mt*16 + h*8 + g;
                        float v = fmaxf(a[mt][h*2]+bb0,0.f)*s0 + fmaxf(a[mt][h*2+1]+bb1,0.f)*s1;
                        v += __shfl_xor_sync(0xffffffffu, v, 1);
                        v += __shfl_xor_sync(0xffffffffu, v, 2);
                        if (t == 0 && r < NP) atomicAdd(&sSelf[r], v);
                    }
                } else {          // w_v1 -> colv
                    int c = c0 - 256;
                    float bb0 = b_v1[c], bb1 = b_v1[c+1];
                    float s0 = 0.f, s1 = 0.f;
#pragma unroll
                    for (int mt = 0; mt < 4; mt++)
#pragma unroll
                    for (int h = 0; h < 2; h++){
                        int r = mt*16 + h*8 + g;
                        if (r < NP){
                            s0 += fmaxf(a[mt][h*2]   + bb0, 0.f);
                            s1 += fmaxf(a[mt][h*2+1] + bb1, 0.f);
                        }
                    }
                    s0 += __shfl_xor_sync(0xffffffffu, s0, 4);
                    s0 += __shfl_xor_sync(0xffffffffu, s0, 8);
                    s0 += __shfl_xor_sync(0xffffffffu, s0, 16);
                    s1 += __shfl_xor_sync(0xffffffffu, s1, 4);
                    s1 += __shfl_xor_sync(0xffffffffu, s1, 8);
                    s1 += __shfl_xor_sync(0xffffffffu, s1, 16);
                    if (g == 0){
                        colv[c]   = s0 * (1.f/NP) * aq1[c];
                        colv[c+1] = s1 * (1.f/NP) * aq1[c+1];
                    }
                }
            });
    __syncthreads();

    // ---- P4: self softmax; avq ----
    if (tid < 32){
        float v0 = tanhf(sSelf[tid]);
        float v1 = (tid + 32 < NP) ? tanhf(sSelf[tid+32]) : -1e30f;
        float mx = wmax(fmaxf(v0, v1));
        float e0 = expf(v0 - mx);
        float e1 = (tid + 32 < NP) ? expf(v1 - mx) : 0.f;
        float s = wsum(e0 + e1);
        sSelf[tid] = e0 / s;
        if (tid + 32 < NP) sSelf[tid+32] = e1 / s;
    }
    gemv8<VDIM>(w_bn, colv, 256, [&](int j, float s){ avqv[j] = fmaxf(s + b_bn[j], 0.f); });
    __syncthreads();

    // ---- P5: sa = self_maps @ vf2 ; ch = 1 + sigmoid(W_ca avq) ----
    for (int p = 0; p < 2; p++){
        int c = tid + p*256; int pc = posk(c);
        float s = 0.f;
        for (int n = 0; n < NP; n++)
            s = fmaf(sSelf[n], __half2float(sA[n*LDAH + pc]), s);
        sav[c] = s;
    }
    gemv8<HDIM>(w_ca, avqv, 512, [&](int j, float s){
        ch[j] = 1.f + 1.f/(1.f + expf(-(s + b_ca[j])));
    });
    __syncthreads();

    // ---- P6: overwrite sA with c_att = video * ch ----
    for (int i = tid; i < NP*VDIM; i += 256){
        int c = i & 511;
        sA[(i >> 9)*LDAH + posk(c)] = __float2half(vf[i] * ch[c]);
    }
    __syncthreads();

    // ---- P7: w_v2 GEMM -> spatial logits (N=256) ----
    gemm_pass<512>(sA, LDAH, g_wph + OFF_V2, 0,
        [&](int col8, float (&a)[4][4]){
            int c0 = col8 + 2*t;
            float s0 = aq2[c0]   * w_sa[c0];
            float s1 = aq2[c0+1] * w_sa[c0+1];
            float bb0 = b_v2[c0], bb1 = b_v2[c0+1];
#pragma unroll
            for (int mt = 0; mt < 4; mt++)
#pragma unroll
            for (int h = 0; h < 2; h++){
                int r = mt*16 + h*8 + g;
                float v = fmaxf(a[mt][h*2]+bb0,0.f)*s0 + fmaxf(a[mt][h*2+1]+bb1,0.f)*s1;
                v += __shfl_xor_sync(0xffffffffu, v, 1);
                v += __shfl_xor_sync(0xffffffffu, v, 2);
                if (t == 0 && r < NP) atomicAdd(&sSp[r], v);
            }
        });
    __syncthreads();

    // ---- P8: spatial softmax ----
    if (tid < 32){
        float v0 = tanhf(sSp[tid]);
        float v1 = (tid + 32 < NP) ? tanhf(sSp[tid+32]) : -1e30f;
        float mx = wmax(fmaxf(v0, v1));
        float e0 = expf(v0 - mx);
        float e1 = (tid + 32 < NP) ? expf(v1 - mx) : 0.f;
        float s = wsum(e0 + e1);
        sSp[tid] = e0 / s;
        if (tid + 32 < NP) sSp[tid+32] = e1 / s;
    }
    __syncthreads();

    // ---- P9: outputs ----
    for (int p = 0; p < 2; p++){
        int c = tid + p*256; int pc = posk(c);
        float cs = 0.f;
        for (int n = 0; n < NP; n++)
            cs = fmaf(sSp[n], __half2float(sA[n*LDAH + pc]), cs);
        float gate = 1.f + 0.5f/(1.f + expf(-sav[c]));
        out[(size_t)item*VDIM + c] = cs * gate;
    }
    if (tid < ADIM)
        out[(size_t)BT*VDIM + (size_t)item*ADIM + tid] = aud[tid];
}

// ---------------------------------------------------------------------------
extern "C" void kernel_launch(void* const* d_in, const int* in_sizes, int n_in,
                              void* d_out, int out_size)
{
    const float* video = (const float*)d_in[0];
    const float* audio = (const float*)d_in[1];
    const float* wq    = (const float*)d_in[2];  const float* bq    = (const float*)d_in[3];
    const float* wk    = (const float*)d_in[4];  const float* bk    = (const float*)d_in[5];
    const float* wv    = (const float*)d_in[6];  const float* bv    = (const float*)d_in[7];
    const float* ln_g  = (const float*)d_in[8];  const float* ln_b  = (const float*)d_in[9];
    const float* w_ave = (const float*)d_in[10]; const float* b_ave = (const float*)d_in[11];
    const float* w_v3  = (const float*)d_in[12]; const float* b_v3  = (const float*)d_in[13];
    const float* w_avt = (const float*)d_in[14]; const float* b_avt = (const float*)d_in[15];
    const float* w_a1  = (const float*)d_in[16]; const float* b_a1  = (const float*)d_in[17];
    const float* w_v1  = (const float*)d_in[18]; const float* b_v1  = (const float*)d_in[19];
    const float* w_bn  = (const float*)d_in[20]; const float* b_bn  = (const float*)d_in[21];
    const float* w_ca  = (const float*)d_in[22]; const float* b_ca  = (const float*)d_in[23];
    const float* w_v2  = (const float*)d_in[24]; const float* b_v2  = (const float*)d_in[25];
    const float* w_a2  = (const float*)d_in[26]; const float* b_a2  = (const float*)d_in[27];
    const float* w_sa  = (const float*)d_in[28]; const float* b_sa  = (const float*)d_in[29];
    float* out = (float*)d_out;

    repack_all<<<3584, 256>>>(wq, wk, wv, w_v3, w_v1, w_v2);

    const int smem1 = 145920;
    const int smem2 = 81920;
    cudaFuncSetAttribute(k1, cudaFuncAttributeMaxDynamicSharedMemorySize, smem1);
    cudaFuncSetAttribute(k2, cudaFuncAttributeMaxDynamicSharedMemorySize, smem2);

    k1<<<BT, 256, smem1>>>(video, bq, bk, bv);
    k2<<<BT, 256, smem2>>>(video, audio, ln_g, ln_b, b_ave, b_v3, w_avt, b_avt,
                           b_a1, b_v1, b_bn, b_ca, b_v2, b_a2, w_sa, b_sa,
                           w_ave, w_a1, w_bn, w_ca, w_a2, out);
}

// round 7
// speedup vs baseline: 4.3501x; 1.2619x over previous
#include <cuda_runtime.h>
#include <cuda_fp16.h>
#include <math.h>

#define NB 256
#define NT 10
#define BT 2560
#define NP 49
#define VDIM 512
#define HDIM 256
#define ADIM 128
#define LDAH 528
#define LDQK2 260
#define LDATT 80

static __device__ float  g_vf2[(size_t)BT * NP * VDIM];
static __device__ __half g_wph[917504];

#define OFF_QK  0
#define OFF_WV  131072
#define OFF_V31 393216
#define OFF_V2  786432

__device__ __forceinline__ float wsum(float v){
#pragma unroll
    for (int s = 16; s > 0; s >>= 1) v += __shfl_xor_sync(0xffffffffu, v, s);
    return v;
}
__device__ __forceinline__ float wmax(float v){
#pragma unroll
    for (int s = 16; s > 0; s >>= 1) v = fmaxf(v, __shfl_xor_sync(0xffffffffu, v, s));
    return v;
}
__device__ __forceinline__ int posk(int k){
    int b = k & 15;
    return (k & ~15) + 4*((b & 7) >> 1) + 2*(b >> 3) + (b & 1);
}
__device__ __forceinline__ void mma16(float (&d)[4], unsigned a0, unsigned a1,
                                      unsigned a2, unsigned a3, unsigned b0, unsigned b1){
    asm volatile("mma.sync.aligned.m16n8k16.row.col.f32.f16.f16.f32 "
        "{%0,%1,%2,%3},{%4,%5,%6,%7},{%8,%9},{%0,%1,%2,%3};"
        : "+f"(d[0]), "+f"(d[1]), "+f"(d[2]), "+f"(d[3])
        : "r"(a0), "r"(a1), "r"(a2), "r"(a3), "r"(b0), "r"(b1));
}

// 16-warp, 2-item GEMM. Warp covers 8 cols (col0 = colbase + warp*8), both items.
// B fragments (shared across items) loaded once per k32. epi(it, col0, acc_it).
template<int KH, class E>
__device__ __forceinline__ void gemm2(const __half* __restrict__ A0,
                                      const __half* __restrict__ A1, int ldah,
                                      const __half* __restrict__ B,
                                      int colbase, E epi)
{
    const int lane = threadIdx.x & 31, warp = threadIdx.x >> 5;
    const int g = lane >> 2, t = lane & 3;
    const int col0 = colbase + warp * 8;
    const int ntb = col0 >> 3;
    constexpr int nk32 = KH >> 5;
    float acc[2][4][4];
#pragma unroll
    for (int it = 0; it < 2; it++)
#pragma unroll
    for (int mt = 0; mt < 4; mt++)
#pragma unroll
    for (int i = 0; i < 4; i++) acc[it][mt][i] = 0.f;

    const __half* Bp = B + (size_t)ntb * nk32 * 256 + lane * 8;
    uint4 bv = *(const uint4*)Bp;
#pragma unroll 2
    for (int k32 = 0; k32 < nk32; k32++){
        uint4 bn;
        if (k32 + 1 < nk32) bn = *(const uint4*)(Bp + (size_t)(k32 + 1) * 256);
#pragma unroll
        for (int s = 0; s < 2; s++){
            const int k0 = k32*32 + s*16 + 4*t;
            unsigned b0 = s ? bv.z : bv.x;
            unsigned b1 = s ? bv.w : bv.y;
#pragma unroll
            for (int it = 0; it < 2; it++){
                const __half* A = it ? A1 : A0;
#pragma unroll
                for (int mt = 0; mt < 4; mt++){
                    uint2 lo = *(const uint2*)(A + (mt*16 +     g)*ldah + k0);
                    uint2 hi = *(const uint2*)(A + (mt*16 + 8 + g)*ldah + k0);
                    mma16(acc[it][mt], lo.x, hi.x, lo.y, hi.y, b0, b1);
                }
            }
        }
        bv = bn;
    }
    epi(0, col0, acc[0]);
    epi(1, col0, acc[1]);
}

// per-item B variant (B in smem), used for attn @ Z
template<int KH, class E>
__device__ __forceinline__ void gemm2b(const __half* __restrict__ A0,
                                       const __half* __restrict__ A1, int ldah,
                                       const __half* __restrict__ B0,
                                       const __half* __restrict__ B1,
                                       int colbase, E epi)
{
    const int lane = threadIdx.x & 31, warp = threadIdx.x >> 5;
    const int g = lane >> 2, t = lane & 3;
    const int col0 = colbase + warp * 8;
    const int ntb = col0 >> 3;
    constexpr int nk32 = KH >> 5;
    float acc[2][4][4];
#pragma unroll
    for (int it = 0; it < 2; it++)
#pragma unroll
    for (int mt = 0; mt < 4; mt++)
#pragma unroll
    for (int i = 0; i < 4; i++) acc[it][mt][i] = 0.f;

#pragma unroll
    for (int k32 = 0; k32 < nk32; k32++){
        uint4 bvv[2];
        bvv[0] = *(const uint4*)(B0 + ((size_t)ntb*nk32 + k32)*256 + lane*8);
        bvv[1] = *(const uint4*)(B1 + ((size_t)ntb*nk32 + k32)*256 + lane*8);
#pragma unroll
        for (int s = 0; s < 2; s++){
            const int k0 = k32*32 + s*16 + 4*t;
#pragma unroll
            for (int it = 0; it < 2; it++){
                const __half* A = it ? A1 : A0;
                unsigned b0 = s ? bvv[it].z : bvv[it].x;
                unsigned b1 = s ? bvv[it].w : bvv[it].y;
#pragma unroll
                for (int mt = 0; mt < 4; mt++){
                    uint2 lo = *(const uint2*)(A + (mt*16 +     g)*ldah + k0);
                    uint2 hi = *(const uint2*)(A + (mt*16 + 8 + g)*ldah + k0);
                    mma16(acc[it][mt], lo.x, hi.x, lo.y, hi.y, b0, b1);
                }
            }
        }
    }
    epi(0, col0, acc[0]);
    epi(1, col0, acc[1]);
}

// 16-warp 2-item GEMV: weight row loaded once, dotted with both x vectors
template<int K, class F>
__device__ __forceinline__ void gemv16(const float* __restrict__ W,
                                       const float* __restrict__ x0,
                                       const float* __restrict__ x1, int N, F f){
    const int lane = threadIdx.x & 31, warp = threadIdx.x >> 5;
    for (int j = warp; j < N; j += 16){
        const float4* wr = (const float4*)(W + (size_t)j * K);
        float s0 = 0.f, s1 = 0.f;
#pragma unroll
        for (int c = 0; c < K/128; c++){
            float4 a = __ldg(wr + lane + 32*c);
            float4 b0 = ((const float4*)x0)[lane + 32*c];
            float4 b1 = ((const float4*)x1)[lane + 32*c];
            s0 = fmaf(a.x,b0.x, fmaf(a.y,b0.y, fmaf(a.z,b0.z, fmaf(a.w,b0.w, s0))));
            s1 = fmaf(a.x,b1.x, fmaf(a.y,b1.y, fmaf(a.z,b1.z, fmaf(a.w,b1.w, s1))));
        }
        s0 = wsum(s0); s1 = wsum(s1);
        if (lane == 0) f(j, s0, s1);
    }
}

// ---- fused weight repack ----
__global__ void repack_all(const float* __restrict__ wq, const float* __restrict__ wk,
                           const float* __restrict__ wv, const float* __restrict__ w_v3,
                           const float* __restrict__ w_v1, const float* __restrict__ w_v2)
{
    int i = blockIdx.x*blockDim.x + threadIdx.x;
    if (i >= 917504) return;
    const float* src; int base;
    if      (i < 65536)  { src = wq;   base = 0; }
    else if (i < 131072) { src = wk;   base = 65536; }
    else if (i < 393216) { src = wv;   base = 131072; }
    else if (i < 524288) { src = w_v3; base = 393216; }
    else if (i < 786432) { src = w_v1; base = 524288; }
    else                 { src = w_v2; base = 786432; }
    int li = i - base;
    int h = li & 7, r = li >> 3;
    int lane = r & 31; r >>= 5;
    int k32 = r & 15;  int nt = r >> 4;
    int g = lane >> 2, t = lane & 3;
    int s = h >> 2, hi = (h >> 1) & 1, lo = h & 1;
    int n = nt*8 + g;
    int k = k32*32 + 16*s + 8*hi + 2*t + lo;
    g_wph[i] = __float2half(src[(size_t)n*512 + k]);
}

// ---------------------------------------------------------------------------
// Kernel 1 (2 items/CTA): self-attention -> g_vf2 (pre-LN)
// ---------------------------------------------------------------------------
__global__ void __launch_bounds__(512, 1)
k1(const float* __restrict__ video, const float* __restrict__ bq,
   const float* __restrict__ bk, const float* __restrict__ bvb)
{
    extern __shared__ __align__(16) unsigned char smraw[];
    __half* sA0  = (__half*)smraw;                     // 64*528 h
    __half* sA1  = sA0 + 64*LDAH;                      // ends 135168 B
    __half* sQKb = (__half*)(smraw + 135168);          // 2 x 64*260 h (66560 B)
    __half* sZpb = (__half*)(smraw + 135168);          // overlays: 2 x 16384 h
    __half* sAtb = (__half*)(smraw + 201728);          // 2 x 64*80 h (20480 B)

    const int tid = threadIdx.x, lane = tid & 31, warp = tid >> 5;
    const int g = lane >> 2, t = lane & 3;
    const int item0 = blockIdx.x * 2;
    const float* vf0 = video + (size_t)item0 * NP * VDIM;
    const float* vf1 = vf0 + NP * VDIM;

#pragma unroll
    for (int it = 0; it < 2; it++){
        __half* sA = it ? sA1 : sA0;
        const float* vf = it ? vf1 : vf0;
        for (int i = tid; i < NP*VDIM; i += 512)
            sA[(i >> 9)*LDAH + posk(i & 511)] = __float2half(vf[i]);
        for (int i = tid; i < 15*LDAH; i += 512)
            sA[49*LDAH + i] = __float2half(0.f);
    }
    for (int i = tid; i < 2*64*LDATT; i += 512) sAtb[i] = __float2half(0.f);
    __syncthreads();

    // ---- q|k GEMM: 2 passes of 128 cols ----
    for (int p = 0; p < 2; p++)
        gemm2<512>(sA0, sA1, LDAH, g_wph + OFF_QK, p*128,
            [&](int it, int col8, float (&a)[4][4]){
                int c = col8 + 2*t;
                float bb0 = (c < 128) ? bq[c] : bk[c-128];
                float bb1 = (c < 128) ? bq[c+1] : bk[c-127];
                __half* dst = sQKb + it*16640 + c;
#pragma unroll
                for (int mt = 0; mt < 4; mt++)
#pragma unroll
                for (int h2 = 0; h2 < 2; h2++){
                    int r = mt*16 + h2*8 + g;
                    dst[r*LDQK2]     = __float2half(a[mt][h2*2]   + bb0);
                    dst[r*LDQK2 + 1] = __float2half(a[mt][h2*2+1] + bb1);
                }
            });
    __syncthreads();

    // ---- softmax(q k^T): 98 rows over 16 warps ----
    for (int R = warp; R < 2*NP; R += 16){
        int it = (R >= NP) ? 1 : 0;
        int n = R - it*NP;
        const __half* q  = sQKb + it*16640 + n*LDQK2;
        const __half* kk = sQKb + it*16640 + 128;
        float a0 = 0.f, a1 = 0.f;
        const int m1 = lane + 32;
        const int m1c = (m1 < NP) ? m1 : 0;
        for (int j = 0; j < 128; j++){
            float qv = __half2float(q[j]);
            a0 = fmaf(qv, __half2float(kk[lane*LDQK2 + j]), a0);
            a1 = fmaf(qv, __half2float(kk[m1c *LDQK2 + j]), a1);
        }
        float v1 = (m1 < NP) ? a1 : -1e30f;
        float mx = wmax(fmaxf(a0, v1));
        float e0 = expf(a0 - mx);
        float e1 = (m1 < NP) ? expf(a1 - mx) : 0.f;
        float s = wsum(e0 + e1);
        float inv = 1.f / s;
        __half* att = sAtb + it*64*LDATT;
        att[n*LDATT + posk(lane)] = __float2half(e0 * inv);
        if (m1 < NP) att[n*LDATT + posk(m1)] = __float2half(e1 * inv);
    }
    __syncthreads();

    // ---- per 256-col half: Z = X @ Wv^T -> packed smem; then out = attn@Z ----
    for (int h = 0; h < 2; h++){
        for (int p = 0; p < 2; p++)
            gemm2<512>(sA0, sA1, LDAH, g_wph + OFF_WV, h*256 + p*128,
                [&](int it, int col8, float (&a)[4][4]){
                    __half* sZp = sZpb + it*16384;
                    int lcb = col8 - h*256;
#pragma unroll
                    for (int mt = 0; mt < 4; mt++)
#pragma unroll
                    for (int h2 = 0; h2 < 2; h2++)
#pragma unroll
                    for (int i = 0; i < 2; i++){
                        int m  = mt*16 + h2*8 + g;
                        int lc = lcb + 2*t + i;
                        int k32 = m >> 5, b = m & 31;
                        int sb = b >> 4, rem = b & 15;
                        int hb = rem >> 3, tp = (rem >> 1) & 3, lo = rem & 1;
                        int off = (((lc >> 3)*2 + k32)*32 + ((lc & 7)*4 + tp))*8
                                  + sb*4 + hb*2 + lo;
                        sZp[off] = __float2half(a[mt][h2*2 + i]);
                    }
                });
        __syncthreads();
        for (int p = 0; p < 2; p++)
            gemm2b<64>(sAtb, sAtb + 64*LDATT, LDATT, sZpb, sZpb + 16384, p*128,
                [&](int it, int col8, float (&a)[4][4]){
                    const float* vf = it ? vf1 : vf0;
                    float* gv = g_vf2 + (size_t)(item0 + it) * NP * VDIM;
#pragma unroll
                    for (int mt = 0; mt < 4; mt++)
#pragma unroll
                    for (int h2 = 0; h2 < 2; h2++){
                        int n = mt*16 + h2*8 + g;
                        if (n < NP){
#pragma unroll
                            for (int i = 0; i < 2; i++){
                                int gc = h*256 + col8 + 2*t + i;
                                gv[n*VDIM + gc] = a[mt][h2*2+i] + bvb[gc] + vf[n*VDIM + gc];
                            }
                        }
                    }
                });
        __syncthreads();
    }
}

// ---------------------------------------------------------------------------
// Kernel 2 (2 items/CTA): LN + all audio-guided branches
// ---------------------------------------------------------------------------
__global__ void __launch_bounds__(512, 1)
k2(const float* __restrict__ video, const float* __restrict__ audio,
   const float* __restrict__ ln_g, const float* __restrict__ ln_b,
   const float* __restrict__ b_ave, const float* __restrict__ b_v3,
   const float* __restrict__ w_avatt, const float* __restrict__ b_avatt,
   const float* __restrict__ b_a1, const float* __restrict__ b_v1,
   const float* __restrict__ b_bn, const float* __restrict__ b_ca,
   const float* __restrict__ b_v2, const float* __restrict__ b_a2,
   const float* __restrict__ w_sa, const float* __restrict__ b_sa,
   const float* __restrict__ w_ave, const float* __restrict__ w_a1,
   const float* __restrict__ w_bn, const float* __restrict__ w_ca,
   const float* __restrict__ w_a2,
   float* __restrict__ out)
{
    extern __shared__ __align__(16) unsigned char smraw[];
    __half* sA0 = (__half*)smraw;
    __half* sA1 = sA0 + 64*LDAH;
    float*  fbf = (float*)(smraw + 135168);    // 2 x 3584 floats
#define FB(it, off) (fbf + (it)*3584 + (off))
    // offsets: colm 0, aq1 512, ch 1024, colv 1536, sav 2048,
    //          havg 2560, aq2 2816, avqv 3072, aud 3328, sSelf 3456, sSp 3520

    const int tid = threadIdx.x, lane = tid & 31, warp = tid >> 5;
    const int g = lane >> 2, t = lane & 3;
    const int item0 = blockIdx.x * 2;
    const float* vf0 = video + (size_t)item0 * NP * VDIM;
    const float* vf1 = vf0 + NP * VDIM;

    // ---- P0: LayerNorm rows of g_vf2 -> sA fp16 permuted ----
    for (int R = warp; R < 2*NP; R += 16){
        int it = (R >= NP) ? 1 : 0;
        int n = R - it*NP;
        const float* src = g_vf2 + (size_t)(item0 + it)*NP*VDIM + n*VDIM;
        __half* sA = it ? sA1 : sA0;
        float s = 0.f, s2 = 0.f;
        for (int j = lane; j < VDIM; j += 32){
            float v = src[j]; s += v; s2 = fmaf(v, v, s2);
        }
        s = wsum(s); s2 = wsum(s2);
        float mu = s * (1.f/VDIM);
        float var = s2 * (1.f/VDIM) - mu*mu;
        float rs = rsqrtf(var + 1e-5f);
        for (int j = lane; j < VDIM; j += 32){
            float v = (src[j] - mu) * rs * ln_g[j] + ln_b[j];
            sA[n*LDAH + posk(j)] = __float2half(v);
        }
    }
    for (int i = tid; i < 15*LDAH; i += 512){
        sA0[49*LDAH + i] = __float2half(0.f);
        sA1[49*LDAH + i] = __float2half(0.f);
    }
    {
        int b0 = item0 / NT, t0 = item0 % NT;
        int b1 = (item0+1) / NT, t1 = (item0+1) % NT;
        const float* ap0 = audio + ((size_t)t0 * NB + b0) * ADIM;
        const float* ap1 = audio + ((size_t)t1 * NB + b1) * ADIM;
        if (tid < ADIM){ FB(0,3328)[tid] = ap0[tid]; FB(1,3328)[tid] = ap1[tid]; }
        if (tid < 64){
#pragma unroll
            for (int it = 0; it < 2; it++){
                FB(it,3456)[tid] = (tid < NP) ? b_avatt[0] : 0.f;
                FB(it,3520)[tid] = (tid < NP) ? b_sa[0]   : 0.f;
            }
        }
    }
    __syncthreads();

    // ---- P1: colm (both items), aq1, aq2 ----
    {
        int c = tid;   // 512 threads, 512 cols
        int pc = posk(c);
        float s0 = 0.f, s1 = 0.f;
        for (int n = 0; n < NP; n++){
            s0 += __half2float(sA0[n*LDAH + pc]);
            s1 += __half2float(sA1[n*LDAH + pc]);
        }
        FB(0,0)[c] = s0 * (1.f/NP);
        FB(1,0)[c] = s1 * (1.f/NP);
    }
    gemv16<ADIM>(w_a1, FB(0,3328), FB(1,3328), 512,
        [&](int j, float s0, float s1){
            FB(0,512)[j] = fmaxf(s0 + b_a1[j], 0.f);
            FB(1,512)[j] = fmaxf(s1 + b_a1[j], 0.f);
        });
    gemv16<ADIM>(w_a2, FB(0,3328), FB(1,3328), 256,
        [&](int j, float s0, float s1){
            FB(0,2816)[j] = fmaxf(s0 + b_a2[j], 0.f);
            FB(1,2816)[j] = fmaxf(s1 + b_a2[j], 0.f);
        });
    __syncthreads();

    // ---- P2: havg ----
    gemv16<VDIM>(w_ave, FB(0,0), FB(1,0), 256,
        [&](int j, float s0, float s1){
            FB(0,2560)[j] = fmaxf(s0 + b_ave[j], 0.f);
            FB(1,2560)[j] = fmaxf(s1 + b_ave[j], 0.f);
        });
    __syncthreads();

    // ---- P3: combined [w_v3 | w_v1] GEMM (N=768): 6 passes of 128 ----
    for (int p = 0; p < 6; p++)
        gemm2<512>(sA0, sA1, LDAH, g_wph + OFF_V31, p*128,
            [&](int it, int col8, float (&a)[4][4]){
                int c0 = col8 + 2*t;
                if (col8 < 256){      // w_v3 -> self logits
                    float s0 = FB(it,2560)[c0]   * w_avatt[c0];
                    float s1 = FB(it,2560)[c0+1] * w_avatt[c0+1];
                    float bb0 = b_v3[c0], bb1 = b_v3[c0+1];
#pragma unroll
                    for (int mt = 0; mt < 4; mt++)
#pragma unroll
                    for (int h2 = 0; h2 < 2; h2++){
                        int r = mt*16 + h2*8 + g;
                        float v = fmaxf(a[mt][h2*2]+bb0,0.f)*s0
                                + fmaxf(a[mt][h2*2+1]+bb1,0.f)*s1;
                        v += __shfl_xor_sync(0xffffffffu, v, 1);
                        v += __shfl_xor_sync(0xffffffffu, v, 2);
                        if (t == 0 && r < NP) atomicAdd(&FB(it,3456)[r], v);
                    }
                } else {              // w_v1 -> colv
                    int c = c0 - 256;
                    float bb0 = b_v1[c], bb1 = b_v1[c+1];
                    float s0 = 0.f, s1 = 0.f;
#pragma unroll
                    for (int mt = 0; mt < 4; mt++)
#pragma unroll
                    for (int h2 = 0; h2 < 2; h2++){
                        int r = mt*16 + h2*8 + g;
                        if (r < NP){
                            s0 += fmaxf(a[mt][h2*2]   + bb0, 0.f);
                            s1 += fmaxf(a[mt][h2*2+1] + bb1, 0.f);
                        }
                    }
                    s0 += __shfl_xor_sync(0xffffffffu, s0, 4);
                    s0 += __shfl_xor_sync(0xffffffffu, s0, 8);
                    s0 += __shfl_xor_sync(0xffffffffu, s0, 16);
                    s1 += __shfl_xor_sync(0xffffffffu, s1, 4);
                    s1 += __shfl_xor_sync(0xffffffffu, s1, 8);
                    s1 += __shfl_xor_sync(0xffffffffu, s1, 16);
                    if (g == 0){
                        FB(it,1536)[c]   = s0 * (1.f/NP) * FB(it,512)[c];
                        FB(it,1536)[c+1] = s1 * (1.f/NP) * FB(it,512)[c+1];
                    }
                }
            });
    __syncthreads();

    // ---- P4: self softmax (warps 0-1) ; avq ----
    if (warp < 2){
        int it = warp;
        float* sl = FB(it,3456);
        float v0 = tanhf(sl[lane]);
        float v1 = (lane + 32 < NP) ? tanhf(sl[lane+32]) : -1e30f;
        float mx = wmax(fmaxf(v0, v1));
        float e0 = expf(v0 - mx);
        float e1 = (lane + 32 < NP) ? expf(v1 - mx) : 0.f;
        float s = wsum(e0 + e1);
        sl[lane] = e0 / s;
        if (lane + 32 < NP) sl[lane+32] = e1 / s;
    }
    gemv16<VDIM>(w_bn, FB(0,1536), FB(1,1536), 256,
        [&](int j, float s0, float s1){
            FB(0,3072)[j] = fmaxf(s0 + b_bn[j], 0.f);
            FB(1,3072)[j] = fmaxf(s1 + b_bn[j], 0.f);
        });
    __syncthreads();

    // ---- P5: sav = self_maps @ vf2 ; ch = 1 + sigmoid(W_ca avq) ----
    {
        int c = tid; int pc = posk(c);
        float s0 = 0.f, s1 = 0.f;
        for (int n = 0; n < NP; n++){
            s0 = fmaf(FB(0,3456)[n], __half2float(sA0[n*LDAH + pc]), s0);
            s1 = fmaf(FB(1,3456)[n], __half2float(sA1[n*LDAH + pc]), s1);
        }
        FB(0,2048)[c] = s0; FB(1,2048)[c] = s1;
    }
    gemv16<HDIM>(w_ca, FB(0,3072), FB(1,3072), 512,
        [&](int j, float s0, float s1){
            FB(0,1024)[j] = 1.f + 1.f/(1.f + expf(-(s0 + b_ca[j])));
            FB(1,1024)[j] = 1.f + 1.f/(1.f + expf(-(s1 + b_ca[j])));
        });
    __syncthreads();

    // ---- P6: overwrite sA with c_att = video * ch ----
#pragma unroll
    for (int it = 0; it < 2; it++){
        __half* sA = it ? sA1 : sA0;
        const float* vf = it ? vf1 : vf0;
        const float* ch = FB(it,1024);
        for (int i = tid; i < NP*VDIM; i += 512){
            int c = i & 511;
            sA[(i >> 9)*LDAH + posk(c)] = __float2half(vf[i] * ch[c]);
        }
    }
    __syncthreads();

    // ---- P7: w_v2 GEMM -> spatial logits (N=256): 2 passes ----
    for (int p = 0; p < 2; p++)
        gemm2<512>(sA0, sA1, LDAH, g_wph + OFF_V2, p*128,
            [&](int it, int col8, float (&a)[4][4]){
                int c0 = col8 + 2*t;
                float s0 = FB(it,2816)[c0]   * w_sa[c0];
                float s1 = FB(it,2816)[c0+1] * w_sa[c0+1];
                float bb0 = b_v2[c0], bb1 = b_v2[c0+1];
#pragma unroll
                for (int mt = 0; mt < 4; mt++)
#pragma unroll
                for (int h2 = 0; h2 < 2; h2++){
                    int r = mt*16 + h2*8 + g;
                    float v = fmaxf(a[mt][h2*2]+bb0,0.f)*s0
                            + fmaxf(a[mt][h2*2+1]+bb1,0.f)*s1;
                    v += __shfl_xor_sync(0xffffffffu, v, 1);
                    v += __shfl_xor_sync(0xffffffffu, v, 2);
                    if (t == 0 && r < NP) atomicAdd(&FB(it,3520)[r], v);
                }
            });
    __syncthreads();

    // ---- P8: spatial softmax (warps 0-1) ----
    if (warp < 2){
        int it = warp;
        float* sp = FB(it,3520);
        float v0 = tanhf(sp[lane]);
        float v1 = (lane + 32 < NP) ? tanhf(sp[lane+32]) : -1e30f;
        float mx = wmax(fmaxf(v0, v1));
        float e0 = expf(v0 - mx);
        float e1 = (lane + 32 < NP) ? expf(v1 - mx) : 0.f;
        float s = wsum(e0 + e1);
        sp[lane] = e0 / s;
        if (lane + 32 < NP) sp[lane+32] = e1 / s;
    }
    __syncthreads();

    // ---- P9: outputs ----
    {
        int c = tid; int pc = posk(c);
        float cs0 = 0.f, cs1 = 0.f;
        for (int n = 0; n < NP; n++){
            cs0 = fmaf(FB(0,3520)[n], __half2float(sA0[n*LDAH + pc]), cs0);
            cs1 = fmaf(FB(1,3520)[n], __half2float(sA1[n*LDAH + pc]), cs1);
        }
        float g0 = 1.f + 0.5f/(1.f + expf(-FB(0,2048)[c]));
        float g1 = 1.f + 0.5f/(1.f + expf(-FB(1,2048)[c]));
        out[(size_t)item0*VDIM + c]     = cs0 * g0;
        out[(size_t)(item0+1)*VDIM + c] = cs1 * g1;
    }
    if (tid < ADIM){
        out[(size_t)BT*VDIM + (size_t)item0*ADIM + tid]     = FB(0,3328)[tid];
        out[(size_t)BT*VDIM + (size_t)(item0+1)*ADIM + tid] = FB(1,3328)[tid];
    }
#undef FB
}

// ---------------------------------------------------------------------------
extern "C" void kernel_launch(void* const* d_in, const int* in_sizes, int n_in,
                              void* d_out, int out_size)
{
    const float* video = (const float*)d_in[0];
    const float* audio = (const float*)d_in[1];
    const float* wq    = (const float*)d_in[2];  const float* bq    = (const float*)d_in[3];
    const float* wk    = (const float*)d_in[4];  const float* bk    = (const float*)d_in[5];
    const float* wv    = (const float*)d_in[6];  const float* bv    = (const float*)d_in[7];
    const float* ln_g  = (const float*)d_in[8];  const float* ln_b  = (const float*)d_in[9];
    const float* w_ave = (const float*)d_in[10]; const float* b_ave = (const float*)d_in[11];
    const float* w_v3  = (const float*)d_in[12]; const float* b_v3  = (const float*)d_in[13];
    const float* w_avt = (const float*)d_in[14]; const float* b_avt = (const float*)d_in[15];
    const float* w_a1  = (const float*)d_in[16]; const float* b_a1  = (const float*)d_in[17];
    const float* w_v1  = (const float*)d_in[18]; const float* b_v1  = (const float*)d_in[19];
    const float* w_bn  = (const float*)d_in[20]; const float* b_bn  = (const float*)d_in[21];
    const float* w_ca  = (const float*)d_in[22]; const float* b_ca  = (const float*)d_in[23];
    const float* w_v2  = (const float*)d_in[24]; const float* b_v2  = (const float*)d_in[25];
    const float* w_a2  = (const float*)d_in[26]; const float* b_a2  = (const float*)d_in[27];
    const float* w_sa  = (const float*)d_in[28]; const float* b_sa  = (const float*)d_in[29];
    float* out = (float*)d_out;

    repack_all<<<3584, 256>>>(wq, wk, wv, w_v3, w_v1, w_v2);

    const int smem1 = 222208;
    const int smem2 = 163840;
    cudaFuncSetAttribute(k1, cudaFuncAttributeMaxDynamicSharedMemorySize, smem1);
    cudaFuncSetAttribute(k2, cudaFuncAttributeMaxDynamicSharedMemorySize, smem2);

    k1<<<BT/2, 512, smem1>>>(video, bq, bk, bv);
    k2<<<BT/2, 512, smem2>>>(video, audio, ln_g, ln_b, b_ave, b_v3, w_avt, b_avt,
                             b_a1, b_v1, b_bn, b_ca, b_v2, b_a2, w_sa, b_sa,
                             w_ave, w_a1, w_bn, w_ca, w_a2, out);
}

// round 8
// speedup vs baseline: 4.8817x; 1.1222x over previous
#include <cuda_runtime.h>
#include <cuda_fp16.h>
#include <math.h>

#define NB 256
#define NT 10
#define BT 2560
#define NP 49
#define VDIM 512
#define HDIM 256
#define ADIM 128
#define LDAH 528
#define LDQK2 260
#define LDATT 80

static __device__ float  g_vf2[(size_t)BT * NP * VDIM];
static __device__ __half g_wph[917504];

#define OFF_QK  0
#define OFF_WV  131072
#define OFF_V31 393216
#define OFF_V2  786432

__device__ __forceinline__ float wsum(float v){
#pragma unroll
    for (int s = 16; s > 0; s >>= 1) v += __shfl_xor_sync(0xffffffffu, v, s);
    return v;
}
__device__ __forceinline__ float wmax(float v){
#pragma unroll
    for (int s = 16; s > 0; s >>= 1) v = fmaxf(v, __shfl_xor_sync(0xffffffffu, v, s));
    return v;
}
__device__ __forceinline__ int posk(int k){
    int b = k & 15;
    return (k & ~15) + 4*((b & 7) >> 1) + 2*(b >> 3) + (b & 1);
}
__device__ __forceinline__ void mma16(float (&d)[4], unsigned a0, unsigned a1,
                                      unsigned a2, unsigned a3, unsigned b0, unsigned b1){
    asm volatile("mma.sync.aligned.m16n8k16.row.col.f32.f16.f16.f32 "
        "{%0,%1,%2,%3},{%4,%5,%6,%7},{%8,%9},{%0,%1,%2,%3};"
        : "+f"(d[0]), "+f"(d[1]), "+f"(d[2]), "+f"(d[3])
        : "r"(a0), "r"(a1), "r"(a2), "r"(a3), "r"(b0), "r"(b1));
}

// M-split mapping: 16 warps = 2 items x 4 mtiles x 2 ngroups.
// Warp computes C[16 x 64]: rows mt*16..+16 of item it, cols col0..col0+64.
// A-fragments: 4 LDS.64 per k32 (vs 32 in N-split). B: packed global (L1-shared).
template<int KH, class E>
__device__ __forceinline__ void gemm_m(const __half* __restrict__ A0,
                                       const __half* __restrict__ A1, int ldah,
                                       const __half* __restrict__ B,
                                       int colbase, E epi)
{
    const int lane = threadIdx.x & 31, warp = threadIdx.x >> 5;
    const int g = lane >> 2, t = lane & 3;
    const int it = warp & 1, mt = (warp >> 1) & 3, ng = warp >> 3;
    const __half* A = (it ? A1 : A0) + (mt*16 + g) * ldah;
    const int col0 = colbase + ng * 64;
    const int ntb = col0 >> 3;
    constexpr int nk32 = KH >> 5;
    float acc[8][4];
#pragma unroll
    for (int nt = 0; nt < 8; nt++)
#pragma unroll
    for (int i = 0; i < 4; i++) acc[nt][i] = 0.f;

    const __half* Bp = B + (size_t)ntb * nk32 * 256 + lane * 8;
    for (int k32 = 0; k32 < nk32; k32++){
        uint4 bv[8];
#pragma unroll
        for (int nt = 0; nt < 8; nt++)
            bv[nt] = *(const uint4*)(Bp + ((size_t)nt * nk32 + k32) * 256);
#pragma unroll
        for (int s = 0; s < 2; s++){
            const int k0 = k32*32 + s*16 + 4*t;
            uint2 lo = *(const uint2*)(A + k0);
            uint2 hi = *(const uint2*)(A + 8*ldah + k0);
#pragma unroll
            for (int nt = 0; nt < 8; nt++)
                mma16(acc[nt], lo.x, hi.x, lo.y, hi.y,
                      s ? bv[nt].z : bv[nt].x, s ? bv[nt].w : bv[nt].y);
        }
    }
    epi(it, mt, col0, acc);
}

// per-item B variant (B in smem), used for attn @ Z
template<int KH, class E>
__device__ __forceinline__ void gemm_mb(const __half* __restrict__ A0,
                                        const __half* __restrict__ A1, int ldah,
                                        const __half* __restrict__ B0,
                                        const __half* __restrict__ B1,
                                        int colbase, E epi)
{
    const int lane = threadIdx.x & 31, warp = threadIdx.x >> 5;
    const int g = lane >> 2, t = lane & 3;
    const int it = warp & 1, mt = (warp >> 1) & 3, ng = warp >> 3;
    const __half* A = (it ? A1 : A0) + (mt*16 + g) * ldah;
    const __half* B = it ? B1 : B0;
    const int col0 = colbase + ng * 64;
    const int ntb = col0 >> 3;
    constexpr int nk32 = KH >> 5;
    float acc[8][4];
#pragma unroll
    for (int nt = 0; nt < 8; nt++)
#pragma unroll
    for (int i = 0; i < 4; i++) acc[nt][i] = 0.f;

    const __half* Bp = B + (size_t)ntb * nk32 * 256 + lane * 8;
#pragma unroll
    for (int k32 = 0; k32 < nk32; k32++){
        uint4 bv[8];
#pragma unroll
        for (int nt = 0; nt < 8; nt++)
            bv[nt] = *(const uint4*)(Bp + ((size_t)nt * nk32 + k32) * 256);
#pragma unroll
        for (int s = 0; s < 2; s++){
            const int k0 = k32*32 + s*16 + 4*t;
            uint2 lo = *(const uint2*)(A + k0);
            uint2 hi = *(const uint2*)(A + 8*ldah + k0);
#pragma unroll
            for (int nt = 0; nt < 8; nt++)
                mma16(acc[nt], lo.x, hi.x, lo.y, hi.y,
                      s ? bv[nt].z : bv[nt].x, s ? bv[nt].w : bv[nt].y);
        }
    }
    epi(it, mt, col0, acc);
}

// 16-warp 2-item GEMV
template<int K, class F>
__device__ __forceinline__ void gemv16(const float* __restrict__ W,
                                       const float* __restrict__ x0,
                                       const float* __restrict__ x1, int N, F f){
    const int lane = threadIdx.x & 31, warp = threadIdx.x >> 5;
    for (int j = warp; j < N; j += 16){
        const float4* wr = (const float4*)(W + (size_t)j * K);
        float s0 = 0.f, s1 = 0.f;
#pragma unroll
        for (int c = 0; c < K/128; c++){
            float4 a = __ldg(wr + lane + 32*c);
            float4 b0 = ((const float4*)x0)[lane + 32*c];
            float4 b1 = ((const float4*)x1)[lane + 32*c];
            s0 = fmaf(a.x,b0.x, fmaf(a.y,b0.y, fmaf(a.z,b0.z, fmaf(a.w,b0.w, s0))));
            s1 = fmaf(a.x,b1.x, fmaf(a.y,b1.y, fmaf(a.z,b1.z, fmaf(a.w,b1.w, s1))));
        }
        s0 = wsum(s0); s1 = wsum(s1);
        if (lane == 0) f(j, s0, s1);
    }
}

// ---- fused weight repack ----
__global__ void repack_all(const float* __restrict__ wq, const float* __restrict__ wk,
                           const float* __restrict__ wv, const float* __restrict__ w_v3,
                           const float* __restrict__ w_v1, const float* __restrict__ w_v2)
{
    int i = blockIdx.x*blockDim.x + threadIdx.x;
    if (i >= 917504) return;
    const float* src; int base;
    if      (i < 65536)  { src = wq;   base = 0; }
    else if (i < 131072) { src = wk;   base = 65536; }
    else if (i < 393216) { src = wv;   base = 131072; }
    else if (i < 524288) { src = w_v3; base = 393216; }
    else if (i < 786432) { src = w_v1; base = 524288; }
    else                 { src = w_v2; base = 786432; }
    int li = i - base;
    int h = li & 7, r = li >> 3;
    int lane = r & 31; r >>= 5;
    int k32 = r & 15;  int nt = r >> 4;
    int g = lane >> 2, t = lane & 3;
    int s = h >> 2, hi = (h >> 1) & 1, lo = h & 1;
    int n = nt*8 + g;
    int k = k32*32 + 16*s + 8*hi + 2*t + lo;
    g_wph[i] = __float2half(src[(size_t)n*512 + k]);
}

// ---------------------------------------------------------------------------
// Kernel 1 (2 items/CTA): self-attention -> g_vf2 (pre-LN)
// ---------------------------------------------------------------------------
__global__ void __launch_bounds__(512, 1)
k1(const float* __restrict__ video, const float* __restrict__ bq,
   const float* __restrict__ bk, const float* __restrict__ bvb)
{
    extern __shared__ __align__(16) unsigned char smraw[];
    __half* sA0  = (__half*)smraw;
    __half* sA1  = sA0 + 64*LDAH;                      // ends 135168 B
    __half* sQKb = (__half*)(smraw + 135168);          // 2 x 64*260 h
    __half* sZpb = (__half*)(smraw + 135168);          // overlays
    __half* sAtb = (__half*)(smraw + 201728);          // 2 x 64*80 h

    const int tid = threadIdx.x, lane = tid & 31, warp = tid >> 5;
    const int g = lane >> 2, t = lane & 3;
    const int item0 = blockIdx.x * 2;
    const float* vf0 = video + (size_t)item0 * NP * VDIM;
    const float* vf1 = vf0 + NP * VDIM;

#pragma unroll
    for (int it = 0; it < 2; it++){
        __half* sA = it ? sA1 : sA0;
        const float* vf = it ? vf1 : vf0;
        for (int i = tid; i < NP*VDIM; i += 512)
            sA[(i >> 9)*LDAH + posk(i & 511)] = __float2half(vf[i]);
        for (int i = tid; i < 15*LDAH; i += 512)
            sA[49*LDAH + i] = __float2half(0.f);
    }
    for (int i = tid; i < 2*64*LDATT; i += 512) sAtb[i] = __float2half(0.f);
    __syncthreads();

    // ---- q|k GEMM: 2 passes of 128 cols ----
    for (int p = 0; p < 2; p++)
        gemm_m<512>(sA0, sA1, LDAH, g_wph + OFF_QK, p*128,
            [&](int it, int mt, int col0, float (&a)[8][4]){
                __half* dstb = sQKb + it*16640;
#pragma unroll
                for (int h2 = 0; h2 < 2; h2++){
                    int r = mt*16 + h2*8 + g;
#pragma unroll
                    for (int nt = 0; nt < 8; nt++)
#pragma unroll
                    for (int i = 0; i < 2; i++){
                        int c = col0 + nt*8 + 2*t + i;
                        float bb = (c < 128) ? bq[c] : bk[c-128];
                        dstb[r*LDQK2 + c] = __float2half(a[nt][h2*2+i] + bb);
                    }
                }
            });
    __syncthreads();

    // ---- softmax(q k^T): 98 rows over 16 warps ----
    for (int R = warp; R < 2*NP; R += 16){
        int it = (R >= NP) ? 1 : 0;
        int n = R - it*NP;
        const __half* q  = sQKb + it*16640 + n*LDQK2;
        const __half* kk = sQKb + it*16640 + 128;
        float a0 = 0.f, a1 = 0.f;
        const int m1 = lane + 32;
        const int m1c = (m1 < NP) ? m1 : 0;
        for (int j = 0; j < 128; j++){
            float qv = __half2float(q[j]);
            a0 = fmaf(qv, __half2float(kk[lane*LDQK2 + j]), a0);
            a1 = fmaf(qv, __half2float(kk[m1c *LDQK2 + j]), a1);
        }
        float v1 = (m1 < NP) ? a1 : -1e30f;
        float mx = wmax(fmaxf(a0, v1));
        float e0 = expf(a0 - mx);
        float e1 = (m1 < NP) ? expf(a1 - mx) : 0.f;
        float s = wsum(e0 + e1);
        float inv = 1.f / s;
        __half* att = sAtb + it*64*LDATT;
        att[n*LDATT + posk(lane)] = __float2half(e0 * inv);
        if (m1 < NP) att[n*LDATT + posk(m1)] = __float2half(e1 * inv);
    }
    __syncthreads();

    // ---- per 256-col half: Z = X @ Wv^T -> packed smem; then out = attn@Z ----
    for (int h = 0; h < 2; h++){
        for (int p = 0; p < 2; p++)
            gemm_m<512>(sA0, sA1, LDAH, g_wph + OFF_WV, h*256 + p*128,
                [&](int it, int mt, int col0, float (&a)[8][4]){
                    __half* sZp = sZpb + it*16384;
#pragma unroll
                    for (int h2 = 0; h2 < 2; h2++){
                        int m = mt*16 + h2*8 + g;
                        int k32 = m >> 5, b = m & 31;
                        int sb = b >> 4, rem = b & 15;
                        int hb = rem >> 3, tp = (rem >> 1) & 3, lo2 = rem & 1;
#pragma unroll
                        for (int nt = 0; nt < 8; nt++)
#pragma unroll
                        for (int i = 0; i < 2; i++){
                            int lc = (col0 - h*256) + nt*8 + 2*t + i;
                            int off = (((lc >> 3)*2 + k32)*32 + ((lc & 7)*4 + tp))*8
                                      + sb*4 + hb*2 + lo2;
                            sZp[off] = __float2half(a[nt][h2*2+i]);
                        }
                    }
                });
        __syncthreads();
        for (int p = 0; p < 2; p++)
            gemm_mb<64>(sAtb, sAtb + 64*LDATT, LDATT, sZpb, sZpb + 16384, p*128,
                [&](int it, int mt, int col0, float (&a)[8][4]){
                    const float* vf = it ? vf1 : vf0;
                    float* gv = g_vf2 + (size_t)(item0 + it) * NP * VDIM;
#pragma unroll
                    for (int h2 = 0; h2 < 2; h2++){
                        int n = mt*16 + h2*8 + g;
                        if (n < NP){
#pragma unroll
                            for (int nt = 0; nt < 8; nt++)
#pragma unroll
                            for (int i = 0; i < 2; i++){
                                int gc = h*256 + col0 + nt*8 + 2*t + i;
                                gv[n*VDIM + gc] = a[nt][h2*2+i] + bvb[gc] + vf[n*VDIM + gc];
                            }
                        }
                    }
                });
        __syncthreads();
    }
}

// ---------------------------------------------------------------------------
// Kernel 2 (2 items/CTA): LN + all audio-guided branches
// ---------------------------------------------------------------------------
__global__ void __launch_bounds__(512, 1)
k2(const float* __restrict__ video, const float* __restrict__ audio,
   const float* __restrict__ ln_g, const float* __restrict__ ln_b,
   const float* __restrict__ b_ave, const float* __restrict__ b_v3,
   const float* __restrict__ w_avatt, const float* __restrict__ b_avatt,
   const float* __restrict__ b_a1, const float* __restrict__ b_v1,
   const float* __restrict__ b_bn, const float* __restrict__ b_ca,
   const float* __restrict__ b_v2, const float* __restrict__ b_a2,
   const float* __restrict__ w_sa, const float* __restrict__ b_sa,
   const float* __restrict__ w_ave, const float* __restrict__ w_a1,
   const float* __restrict__ w_bn, const float* __restrict__ w_ca,
   const float* __restrict__ w_a2,
   float* __restrict__ out)
{
    extern __shared__ __align__(16) unsigned char smraw[];
    __half* sA0 = (__half*)smraw;
    __half* sA1 = sA0 + 64*LDAH;
    float*  fbf = (float*)(smraw + 135168);    // 2 x 3584 floats
#define FB(it, off) (fbf + (it)*3584 + (off))
    // colm 0, aq1 512, ch 1024, colv 1536, sav 2048,
    // havg 2560, aq2 2816, avqv 3072, aud 3328, sSelf 3456, sSp 3520

    const int tid = threadIdx.x, lane = tid & 31, warp = tid >> 5;
    const int g = lane >> 2, t = lane & 3;
    const int item0 = blockIdx.x * 2;
    const float* vf0 = video + (size_t)item0 * NP * VDIM;
    const float* vf1 = vf0 + NP * VDIM;

    // ---- P0: LayerNorm rows of g_vf2 -> sA fp16 permuted ----
    for (int R = warp; R < 2*NP; R += 16){
        int it = (R >= NP) ? 1 : 0;
        int n = R - it*NP;
        const float* src = g_vf2 + (size_t)(item0 + it)*NP*VDIM + n*VDIM;
        __half* sA = it ? sA1 : sA0;
        float s = 0.f, s2 = 0.f;
        for (int j = lane; j < VDIM; j += 32){
            float v = src[j]; s += v; s2 = fmaf(v, v, s2);
        }
        s = wsum(s); s2 = wsum(s2);
        float mu = s * (1.f/VDIM);
        float var = s2 * (1.f/VDIM) - mu*mu;
        float rs = rsqrtf(var + 1e-5f);
        for (int j = lane; j < VDIM; j += 32){
            float v = (src[j] - mu) * rs * ln_g[j] + ln_b[j];
            sA[n*LDAH + posk(j)] = __float2half(v);
        }
    }
    for (int i = tid; i < 15*LDAH; i += 512){
        sA0[49*LDAH + i] = __float2half(0.f);
        sA1[49*LDAH + i] = __float2half(0.f);
    }
    {
        int b0 = item0 / NT, t0 = item0 % NT;
        int b1 = (item0+1) / NT, t1 = (item0+1) % NT;
        const float* ap0 = audio + ((size_t)t0 * NB + b0) * ADIM;
        const float* ap1 = audio + ((size_t)t1 * NB + b1) * ADIM;
        if (tid < ADIM){ FB(0,3328)[tid] = ap0[tid]; FB(1,3328)[tid] = ap1[tid]; }
        FB(0,1536)[tid] = 0.f;   // colv partials
        FB(1,1536)[tid] = 0.f;
        if (tid < 64){
#pragma unroll
            for (int it = 0; it < 2; it++){
                FB(it,3456)[tid] = (tid < NP) ? b_avatt[0] : 0.f;
                FB(it,3520)[tid] = (tid < NP) ? b_sa[0]   : 0.f;
            }
        }
    }
    __syncthreads();

    // ---- P1: colm, aq1, aq2 ----
    {
        int c = tid;
        int pc = posk(c);
        float s0 = 0.f, s1 = 0.f;
        for (int n = 0; n < NP; n++){
            s0 += __half2float(sA0[n*LDAH + pc]);
            s1 += __half2float(sA1[n*LDAH + pc]);
        }
        FB(0,0)[c] = s0 * (1.f/NP);
        FB(1,0)[c] = s1 * (1.f/NP);
    }
    gemv16<ADIM>(w_a1, FB(0,3328), FB(1,3328), 512,
        [&](int j, float s0, float s1){
            FB(0,512)[j] = fmaxf(s0 + b_a1[j], 0.f);
            FB(1,512)[j] = fmaxf(s1 + b_a1[j], 0.f);
        });
    gemv16<ADIM>(w_a2, FB(0,3328), FB(1,3328), 256,
        [&](int j, float s0, float s1){
            FB(0,2816)[j] = fmaxf(s0 + b_a2[j], 0.f);
            FB(1,2816)[j] = fmaxf(s1 + b_a2[j], 0.f);
        });
    __syncthreads();

    // ---- P2: havg ----
    gemv16<VDIM>(w_ave, FB(0,0), FB(1,0), 256,
        [&](int j, float s0, float s1){
            FB(0,2560)[j] = fmaxf(s0 + b_ave[j], 0.f);
            FB(1,2560)[j] = fmaxf(s1 + b_ave[j], 0.f);
        });
    __syncthreads();

    // ---- P3: combined [w_v3 | w_v1] GEMM (N=768): 6 passes of 128 ----
    for (int p = 0; p < 6; p++)
        gemm_m<512>(sA0, sA1, LDAH, g_wph + OFF_V31, p*128,
            [&](int it, int mt, int col0, float (&a)[8][4]){
                if (col0 < 256){      // w_v3 -> self logits
#pragma unroll
                    for (int h2 = 0; h2 < 2; h2++){
                        int r = mt*16 + h2*8 + g;
                        float v = 0.f;
#pragma unroll
                        for (int nt = 0; nt < 8; nt++)
#pragma unroll
                        for (int i = 0; i < 2; i++){
                            int c = col0 + nt*8 + 2*t + i;
                            v += fmaxf(a[nt][h2*2+i] + b_v3[c], 0.f)
                                 * FB(it,2560)[c] * w_avatt[c];
                        }
                        v += __shfl_xor_sync(0xffffffffu, v, 1);
                        v += __shfl_xor_sync(0xffffffffu, v, 2);
                        if (t == 0 && r < NP) atomicAdd(&FB(it,3456)[r], v);
                    }
                } else {              // w_v1 -> colv partials
                    int rb = mt*16 + g;
                    float m0 = (rb < NP) ? 1.f : 0.f;
                    float m1 = (rb + 8 < NP) ? 1.f : 0.f;
#pragma unroll
                    for (int nt = 0; nt < 8; nt++)
#pragma unroll
                    for (int i = 0; i < 2; i++){
                        int c = col0 - 256 + nt*8 + 2*t + i;
                        float bb = b_v1[c];
                        float pv = m0*fmaxf(a[nt][i]   + bb, 0.f)
                                 + m1*fmaxf(a[nt][2+i] + bb, 0.f);
                        pv += __shfl_xor_sync(0xffffffffu, pv, 4);
                        pv += __shfl_xor_sync(0xffffffffu, pv, 8);
                        pv += __shfl_xor_sync(0xffffffffu, pv, 16);
                        if (g == 0) atomicAdd(&FB(it,1536)[c], pv);
                    }
                }
            });
    __syncthreads();

    // ---- finalize colv; self softmax ----
    {
        int it = tid >> 8, c2 = (tid & 255)*2;
#pragma unroll
        for (int d = 0; d < 2; d++){
            int c = c2 + d;
            FB(it,1536)[c] = FB(it,1536)[c] * (1.f/NP) * FB(it,512)[c];
        }
    }
    if (warp < 2){
        int it = warp;
        float* sl = FB(it,3456);
        float v0 = tanhf(sl[lane]);
        float v1 = (lane + 32 < NP) ? tanhf(sl[lane+32]) : -1e30f;
        float mx = wmax(fmaxf(v0, v1));
        float e0 = expf(v0 - mx);
        float e1 = (lane + 32 < NP) ? expf(v1 - mx) : 0.f;
        float s = wsum(e0 + e1);
        sl[lane] = e0 / s;
        if (lane + 32 < NP) sl[lane+32] = e1 / s;
    }
    __syncthreads();

    // ---- P4: avq = relu(W_bn colv) ----
    gemv16<VDIM>(w_bn, FB(0,1536), FB(1,1536), 256,
        [&](int j, float s0, float s1){
            FB(0,3072)[j] = fmaxf(s0 + b_bn[j], 0.f);
            FB(1,3072)[j] = fmaxf(s1 + b_bn[j], 0.f);
        });
    __syncthreads();

    // ---- P5: sav = self_maps @ vf2 ; ch = 1 + sigmoid(W_ca avq) ----
    {
        int c = tid; int pc = posk(c);
        float s0 = 0.f, s1 = 0.f;
        for (int n = 0; n < NP; n++){
            s0 = fmaf(FB(0,3456)[n], __half2float(sA0[n*LDAH + pc]), s0);
            s1 = fmaf(FB(1,3456)[n], __half2float(sA1[n*LDAH + pc]), s1);
        }
        FB(0,2048)[c] = s0; FB(1,2048)[c] = s1;
    }
    gemv16<HDIM>(w_ca, FB(0,3072), FB(1,3072), 512,
        [&](int j, float s0, float s1){
            FB(0,1024)[j] = 1.f + 1.f/(1.f + expf(-(s0 + b_ca[j])));
            FB(1,1024)[j] = 1.f + 1.f/(1.f + expf(-(s1 + b_ca[j])));
        });
    __syncthreads();

    // ---- P6: overwrite sA with c_att = video * ch ----
#pragma unroll
    for (int it = 0; it < 2; it++){
        __half* sA = it ? sA1 : sA0;
        const float* vf = it ? vf1 : vf0;
        const float* ch = FB(it,1024);
        for (int i = tid; i < NP*VDIM; i += 512){
            int c = i & 511;
            sA[(i >> 9)*LDAH + posk(c)] = __float2half(vf[i] * ch[c]);
        }
    }
    __syncthreads();

    // ---- P7: w_v2 GEMM -> spatial logits (N=256): 2 passes ----
    for (int p = 0; p < 2; p++)
        gemm_m<512>(sA0, sA1, LDAH, g_wph + OFF_V2, p*128,
            [&](int it, int mt, int col0, float (&a)[8][4]){
#pragma unroll
                for (int h2 = 0; h2 < 2; h2++){
                    int r = mt*16 + h2*8 + g;
                    float v = 0.f;
#pragma unroll
                    for (int nt = 0; nt < 8; nt++)
#pragma unroll
                    for (int i = 0; i < 2; i++){
                        int c = col0 + nt*8 + 2*t + i;
                        v += fmaxf(a[nt][h2*2+i] + b_v2[c], 0.f)
                             * FB(it,2816)[c] * w_sa[c];
                    }
                    v += __shfl_xor_sync(0xffffffffu, v, 1);
                    v += __shfl_xor_sync(0xffffffffu, v, 2);
                    if (t == 0 && r < NP) atomicAdd(&FB(it,3520)[r], v);
                }
            });
    __syncthreads();

    // ---- P8: spatial softmax ----
    if (warp < 2){
        int it = warp;
        float* sp = FB(it,3520);
        float v0 = tanhf(sp[lane]);
        float v1 = (lane + 32 < NP) ? tanhf(sp[lane+32]) : -1e30f;
        float mx = wmax(fmaxf(v0, v1));
        float e0 = expf(v0 - mx);
        float e1 = (lane + 32 < NP) ? expf(v1 - mx) : 0.f;
        float s = wsum(e0 + e1);
        sp[lane] = e0 / s;
        if (lane + 32 < NP) sp[lane+32] = e1 / s;
    }
    __syncthreads();

    // ---- P9: outputs ----
    {
        int c = tid; int pc = posk(c);
        float cs0 = 0.f, cs1 = 0.f;
        for (int n = 0; n < NP; n++){
            cs0 = fmaf(FB(0,3520)[n], __half2float(sA0[n*LDAH + pc]), cs0);
            cs1 = fmaf(FB(1,3520)[n], __half2float(sA1[n*LDAH + pc]), cs1);
        }
        float g0 = 1.f + 0.5f/(1.f + expf(-FB(0,2048)[c]));
        float g1 = 1.f + 0.5f/(1.f + expf(-FB(1,2048)[c]));
        out[(size_t)item0*VDIM + c]     = cs0 * g0;
        out[(size_t)(item0+1)*VDIM + c] = cs1 * g1;
    }
    if (tid < ADIM){
        out[(size_t)BT*VDIM + (size_t)item0*ADIM + tid]     = FB(0,3328)[tid];
        out[(size_t)BT*VDIM + (size_t)(item0+1)*ADIM + tid] = FB(1,3328)[tid];
    }
#undef FB
}

// ---------------------------------------------------------------------------
extern "C" void kernel_launch(void* const* d_in, const int* in_sizes, int n_in,
                              void* d_out, int out_size)
{
    const float* video = (const float*)d_in[0];
    const float* audio = (const float*)d_in[1];
    const float* wq    = (const float*)d_in[2];  const float* bq    = (const float*)d_in[3];
    const float* wk    = (const float*)d_in[4];  const float* bk    = (const float*)d_in[5];
    const float* wv    = (const float*)d_in[6];  const float* bv    = (const float*)d_in[7];
    const float* ln_g  = (const float*)d_in[8];  const float* ln_b  = (const float*)d_in[9];
    const float* w_ave = (const float*)d_in[10]; const float* b_ave = (const float*)d_in[11];
    const float* w_v3  = (const float*)d_in[12]; const float* b_v3  = (const float*)d_in[13];
    const float* w_avt = (const float*)d_in[14]; const float* b_avt = (const float*)d_in[15];
    const float* w_a1  = (const float*)d_in[16]; const float* b_a1  = (const float*)d_in[17];
    const float* w_v1  = (const float*)d_in[18]; const float* b_v1  = (const float*)d_in[19];
    const float* w_bn  = (const float*)d_in[20]; const float* b_bn  = (const float*)d_in[21];
    const float* w_ca  = (const float*)d_in[22]; const float* b_ca  = (const float*)d_in[23];
    const float* w_v2  = (const float*)d_in[24]; const float* b_v2  = (const float*)d_in[25];
    const float* w_a2  = (const float*)d_in[26]; const float* b_a2  = (const float*)d_in[27];
    const float* w_sa  = (const float*)d_in[28]; const float* b_sa  = (const float*)d_in[29];
    float* out = (float*)d_out;

    repack_all<<<3584, 256>>>(wq, wk, wv, w_v3, w_v1, w_v2);

    const int smem1 = 222208;
    const int smem2 = 163840;
    cudaFuncSetAttribute(k1, cudaFuncAttributeMaxDynamicSharedMemorySize, smem1);
    cudaFuncSetAttribute(k2, cudaFuncAttributeMaxDynamicSharedMemorySize, smem2);

    k1<<<BT/2, 512, smem1>>>(video, bq, bk, bv);
    k2<<<BT/2, 512, smem2>>>(video, audio, ln_g, ln_b, b_ave, b_v3, w_avt, b_avt,
                             b_a1, b_v1, b_bn, b_ca, b_v2, b_a2, w_sa, b_sa,
                             w_ave, w_a1, w_bn, w_ca, w_a2, out);
}